// round 7
// baseline (speedup 1.0000x reference)
#include <cuda_runtime.h>
#include <math.h>
#include <stdint.h>

// ---------------------------------------------------------------------------
// Problem constants
// ---------------------------------------------------------------------------
#define BATCH   2
#define SEQ     4096
#define DMODEL  1024
#define DINNER  2048
#define NHEADS  16
#define HDIM    128
#define DSTATE  16
#define DCONV   4
#define CHUNK   64
#define NCHUNK  (SEQ / CHUNK)      // 64
#define M_ROWS  (BATCH * SEQ)      // 8192
#define NPROJ   (NHEADS + 2*DSTATE) // 48
#define ROWW    (2 * DINNER)        // g_xz row width
#define LN_EPS  1e-5f

// ---------------------------------------------------------------------------
// Scratch (static device globals -- no allocation allowed)
// ---------------------------------------------------------------------------
__device__ float  g_xz[(size_t)M_ROWS * ROWW];          // [xe | z]
__device__ float  g_proj[(size_t)M_ROWS * NPROJ];       // dt_raw | B | C
__device__ float  g_y[(size_t)M_ROWS * DINNER];         // raw gated y (pre-LN)
__device__ float  g_S[(size_t)BATCH*NHEADS*NCHUNK*HDIM*DSTATE];
__device__ float  g_P[(size_t)BATCH*NHEADS*NCHUNK*HDIM];
__device__ float2 g_lnstats[M_ROWS];                    // {mu, rstd} per row

// ---------------------------------------------------------------------------
// Helpers (IEEE-accurate transcendentals; tf32 GEMMs own the error budget)
// ---------------------------------------------------------------------------
__device__ __forceinline__ uint32_t tf32_rn(float x) {
    uint32_t r;
    asm("cvt.rna.tf32.f32 %0, %1;" : "=r"(r) : "f"(x));
    return r;
}
__device__ __forceinline__ uint4 cvt4(float4 v) {
    uint4 u;
    u.x = tf32_rn(v.x); u.y = tf32_rn(v.y); u.z = tf32_rn(v.z); u.w = tf32_rn(v.w);
    return u;
}
__device__ __forceinline__ void mma_tf32(float* c, const uint32_t* a, const uint32_t* b) {
    asm volatile(
        "mma.sync.aligned.m16n8k8.row.col.f32.tf32.tf32.f32 "
        "{%0,%1,%2,%3},{%4,%5,%6,%7},{%8,%9},{%0,%1,%2,%3};"
        : "+f"(c[0]), "+f"(c[1]), "+f"(c[2]), "+f"(c[3])
        : "r"(a[0]), "r"(a[1]), "r"(a[2]), "r"(a[3]), "r"(b[0]), "r"(b[1]));
}
__device__ __forceinline__ float softplus_acc(float x) {
    return (x > 20.f) ? x : log1pf(expf(x));
}
__device__ __forceinline__ float silu_acc(float v) {
    return v / (1.f + expf(-v));
}
__device__ __forceinline__ float4 ln_apply(float4 v, float mu, float rs,
                                           const float* __restrict__ g,
                                           const float* __restrict__ b, int col) {
    float4 gg = *(const float4*)(g + col);
    float4 bb = *(const float4*)(b + col);
    v.x = (v.x - mu) * rs * gg.x + bb.x;
    v.y = (v.y - mu) * rs * gg.y + bb.y;
    v.z = (v.z - mu) * rs * gg.z + bb.z;
    v.w = (v.w - mu) * rs * gg.w + bb.w;
    return v;
}

// ---------------------------------------------------------------------------
// TF32 tensor-core GEMM (R2/R6 configuration -- measured good):
// 256 threads, BM=BN=128, BK=16, warp tile 64x32, double-buffered smem.
// ---------------------------------------------------------------------------
__global__ __launch_bounds__(256, 2) void gemm_tf32(
    const float* __restrict__ A, const float* __restrict__ B,
    float* __restrict__ C, int M, int N, int K)
{
    __shared__ uint32_t As[2][128][20];
    __shared__ uint32_t Bs[2][16][136];

    const int tid  = threadIdx.x;
    const int warp = tid >> 5, lane = tid & 31;
    const int g    = lane >> 2, q = lane & 3;
    const int wm   = (warp & 1) * 64;
    const int wn   = (warp >> 1) * 32;
    const int m0   = blockIdx.y * 128;
    const int n0   = blockIdx.x * 128;

    const int ar = tid >> 1;
    const int ac = (tid & 1) * 8;
    const int br = tid >> 4;
    const int bc = (tid & 15) * 8;

    const float* Aptr = A + (size_t)(m0 + ar) * K + ac;
    const float* Bptr = B + (size_t)br * N + n0 + bc;

    float acc[4][4][4];
#pragma unroll
    for (int i = 0; i < 4; i++)
#pragma unroll
        for (int j = 0; j < 4; j++)
#pragma unroll
            for (int k = 0; k < 4; k++) acc[i][j][k] = 0.f;

    {
        float4 a0 = *(const float4*)(Aptr);
        float4 a1 = *(const float4*)(Aptr + 4);
        float4 b0 = *(const float4*)(Bptr);
        float4 b1 = *(const float4*)(Bptr + 4);
        *(uint4*)&As[0][ar][ac]     = cvt4(a0);
        *(uint4*)&As[0][ar][ac + 4] = cvt4(a1);
        *(uint4*)&Bs[0][br][bc]     = cvt4(b0);
        *(uint4*)&Bs[0][br][bc + 4] = cvt4(b1);
    }
    __syncthreads();

    const int nk = K >> 4;
    for (int kt = 0; kt < nk; kt++) {
        const int cur = kt & 1;

        float4 na0, na1, nb0, nb1;
        if (kt + 1 < nk) {
            const float* Ap = Aptr + (kt + 1) * 16;
            const float* Bp = Bptr + (size_t)(kt + 1) * 16 * N;
            na0 = *(const float4*)(Ap);
            na1 = *(const float4*)(Ap + 4);
            nb0 = *(const float4*)(Bp);
            nb1 = *(const float4*)(Bp + 4);
        }

#pragma unroll
        for (int ks = 0; ks < 2; ks++) {
            uint32_t af[4][4], bf[4][2];
            const int kk = ks * 8 + q;
#pragma unroll
            for (int tm = 0; tm < 4; tm++) {
                const int r = wm + tm * 16 + g;
                af[tm][0] = As[cur][r][kk];
                af[tm][1] = As[cur][r + 8][kk];
                af[tm][2] = As[cur][r][kk + 4];
                af[tm][3] = As[cur][r + 8][kk + 4];
            }
#pragma unroll
            for (int tn = 0; tn < 4; tn++) {
                const int n = wn + tn * 8 + g;
                bf[tn][0] = Bs[cur][kk][n];
                bf[tn][1] = Bs[cur][kk + 4][n];
            }
#pragma unroll
            for (int tm = 0; tm < 4; tm++)
#pragma unroll
                for (int tn = 0; tn < 4; tn++)
                    mma_tf32(acc[tm][tn], af[tm], bf[tn]);
        }

        if (kt + 1 < nk) {
            const int nxt = cur ^ 1;
            *(uint4*)&As[nxt][ar][ac]     = cvt4(na0);
            *(uint4*)&As[nxt][ar][ac + 4] = cvt4(na1);
            *(uint4*)&Bs[nxt][br][bc]     = cvt4(nb0);
            *(uint4*)&Bs[nxt][br][bc + 4] = cvt4(nb1);
        }
        __syncthreads();
    }

#pragma unroll
    for (int tm = 0; tm < 4; tm++) {
        const int row = m0 + wm + tm * 16 + g;
#pragma unroll
        for (int tn = 0; tn < 4; tn++) {
            const int col = n0 + wn + tn * 8 + 2 * q;
            *(float2*)&C[(size_t)row * N + col] =
                make_float2(acc[tm][tn][0], acc[tm][tn][1]);
            *(float2*)&C[(size_t)(row + 8) * N + col] =
                make_float2(acc[tm][tn][2], acc[tm][tn][3]);
        }
    }
}

// ---------------------------------------------------------------------------
// GEMM2 variant: applies LayerNorm to A rows during staging.
// A is raw g_y; per-row {mu, rstd} from g_lnstats; per-col ln_g/ln_b.
// ---------------------------------------------------------------------------
__global__ __launch_bounds__(256, 2) void gemm_tf32_ln(
    const float* __restrict__ A, const float* __restrict__ B,
    float* __restrict__ C, int M, int N, int K,
    const float* __restrict__ ln_g, const float* __restrict__ ln_b)
{
    __shared__ uint32_t As[2][128][20];
    __shared__ uint32_t Bs[2][16][136];

    const int tid  = threadIdx.x;
    const int warp = tid >> 5, lane = tid & 31;
    const int g    = lane >> 2, q = lane & 3;
    const int wm   = (warp & 1) * 64;
    const int wn   = (warp >> 1) * 32;
    const int m0   = blockIdx.y * 128;
    const int n0   = blockIdx.x * 128;

    const int ar = tid >> 1;
    const int ac = (tid & 1) * 8;
    const int br = tid >> 4;
    const int bc = (tid & 15) * 8;

    const float* Aptr = A + (size_t)(m0 + ar) * K + ac;
    const float* Bptr = B + (size_t)br * N + n0 + bc;

    const float2 st = g_lnstats[m0 + ar];
    const float mu = st.x, rs = st.y;

    float acc[4][4][4];
#pragma unroll
    for (int i = 0; i < 4; i++)
#pragma unroll
        for (int j = 0; j < 4; j++)
#pragma unroll
            for (int k = 0; k < 4; k++) acc[i][j][k] = 0.f;

    {
        float4 a0 = ln_apply(*(const float4*)(Aptr),     mu, rs, ln_g, ln_b, ac);
        float4 a1 = ln_apply(*(const float4*)(Aptr + 4), mu, rs, ln_g, ln_b, ac + 4);
        float4 b0 = *(const float4*)(Bptr);
        float4 b1 = *(const float4*)(Bptr + 4);
        *(uint4*)&As[0][ar][ac]     = cvt4(a0);
        *(uint4*)&As[0][ar][ac + 4] = cvt4(a1);
        *(uint4*)&Bs[0][br][bc]     = cvt4(b0);
        *(uint4*)&Bs[0][br][bc + 4] = cvt4(b1);
    }
    __syncthreads();

    const int nk = K >> 4;
    for (int kt = 0; kt < nk; kt++) {
        const int cur = kt & 1;

        float4 na0, na1, nb0, nb1;
        if (kt + 1 < nk) {
            const float* Ap = Aptr + (kt + 1) * 16;
            const float* Bp = Bptr + (size_t)(kt + 1) * 16 * N;
            const int colb = (kt + 1) * 16 + ac;
            na0 = ln_apply(*(const float4*)(Ap),     mu, rs, ln_g, ln_b, colb);
            na1 = ln_apply(*(const float4*)(Ap + 4), mu, rs, ln_g, ln_b, colb + 4);
            nb0 = *(const float4*)(Bp);
            nb1 = *(const float4*)(Bp + 4);
        }

#pragma unroll
        for (int ks = 0; ks < 2; ks++) {
            uint32_t af[4][4], bf[4][2];
            const int kk = ks * 8 + q;
#pragma unroll
            for (int tm = 0; tm < 4; tm++) {
                const int r = wm + tm * 16 + g;
                af[tm][0] = As[cur][r][kk];
                af[tm][1] = As[cur][r + 8][kk];
                af[tm][2] = As[cur][r][kk + 4];
                af[tm][3] = As[cur][r + 8][kk + 4];
            }
#pragma unroll
            for (int tn = 0; tn < 4; tn++) {
                const int n = wn + tn * 8 + g;
                bf[tn][0] = Bs[cur][kk][n];
                bf[tn][1] = Bs[cur][kk + 4][n];
            }
#pragma unroll
            for (int tm = 0; tm < 4; tm++)
#pragma unroll
                for (int tn = 0; tn < 4; tn++)
                    mma_tf32(acc[tm][tn], af[tm], bf[tn]);
        }

        if (kt + 1 < nk) {
            const int nxt = cur ^ 1;
            *(uint4*)&As[nxt][ar][ac]     = cvt4(na0);
            *(uint4*)&As[nxt][ar][ac + 4] = cvt4(na1);
            *(uint4*)&Bs[nxt][br][bc]     = cvt4(nb0);
            *(uint4*)&Bs[nxt][br][bc + 4] = cvt4(nb1);
        }
        __syncthreads();
    }

#pragma unroll
    for (int tm = 0; tm < 4; tm++) {
        const int row = m0 + wm + tm * 16 + g;
#pragma unroll
        for (int tn = 0; tn < 4; tn++) {
            const int col = n0 + wn + tn * 8 + 2 * q;
            *(float2*)&C[(size_t)row * N + col] =
                make_float2(acc[tm][tn][0], acc[tm][tn][1]);
            *(float2*)&C[(size_t)(row + 8) * N + col] =
                make_float2(acc[tm][tn][2], acc[tm][tn][3]);
        }
    }
}

// ---------------------------------------------------------------------------
// proj + fused depthwise conv + silu:
// proj[M,48] = silu(conv(xe)+bias) @ W_xproj, xc computed in smem per k-tile.
// ---------------------------------------------------------------------------
__global__ __launch_bounds__(256) void proj_conv_kernel(
    const float* __restrict__ W_xproj, const float* __restrict__ conv_w,
    const float* __restrict__ conv_b)
{
    __shared__ float xr[35][64];     // xe rows m0-3 .. m0+31 for this k-tile
    __shared__ float ws[64][NPROJ];
    __shared__ float xs[32][64];     // conv+silu result
    const int tid = threadIdx.x;
    const int m0  = blockIdx.x * 32;
    const bool seqstart = ((m0 & (SEQ - 1)) == 0);

    float acc[6];
#pragma unroll
    for (int o = 0; o < 6; o++) acc[o] = 0.f;

    for (int k0 = 0; k0 < DINNER; k0 += 64) {
        for (int t = tid; t < 35 * 64; t += 256) {
            int rr = t >> 6, cc = t & 63;
            float v = 0.f;
            if (!(seqstart && rr < 3))
                v = g_xz[(size_t)(m0 - 3 + rr) * ROWW + k0 + cc];
            xr[rr][cc] = v;
        }
        for (int t = tid; t < 64 * NPROJ; t += 256) {
            int kk = t / NPROJ;
            int j  = t - kk * NPROJ;
            ws[kk][j] = W_xproj[(size_t)(k0 + kk) * NPROJ + j];
        }
        __syncthreads();

        for (int t = tid; t < 32 * 64; t += 256) {
            int r  = t >> 6, cc = t & 63;
            int ch = k0 + cc;
            float4 wv = *(const float4*)(conv_w + (size_t)ch * 4);
            float a = conv_b[ch];
            a = fmaf(wv.x, xr[r][cc],     a);
            a = fmaf(wv.y, xr[r + 1][cc], a);
            a = fmaf(wv.z, xr[r + 2][cc], a);
            a = fmaf(wv.w, xr[r + 3][cc], a);
            xs[r][cc] = silu_acc(a);
        }
        __syncthreads();

#pragma unroll
        for (int o = 0; o < 6; o++) {
            int oi = o * 256 + tid;
            int r  = oi / NPROJ;
            int j  = oi - r * NPROJ;
            float a = acc[o];
#pragma unroll 8
            for (int kk = 0; kk < 64; kk++)
                a = fmaf(xs[r][kk], ws[kk][j], a);
            acc[o] = a;
        }
        __syncthreads();
    }
#pragma unroll
    for (int o = 0; o < 6; o++) {
        int oi = o * 256 + tid;
        int r  = oi / NPROJ;
        int j  = oi - r * NPROJ;
        g_proj[(size_t)(m0 + r) * NPROJ + j] = acc[o];
    }
}

// ---------------------------------------------------------------------------
// Chunked scan, pass 1: rolling-window conv+silu on xe, dt/decay on the fly.
// g_P is the PRODUCT of all 64 per-step decays (NOT exp(Ah*cum_final)).
// ---------------------------------------------------------------------------
__global__ __launch_bounds__(128) void scan_pass1(
    const float* __restrict__ W_dt, const float* __restrict__ b_dt,
    const float* __restrict__ A_log, const float* __restrict__ conv_w,
    const float* __restrict__ conv_b)
{
    const int blk = blockIdx.x;
    const int c   = blk & (NCHUNK - 1);
    const int h   = (blk >> 6) & (NHEADS - 1);
    const int b   = blk >> 10;
    const int d   = threadIdx.x;
    const int i   = h * HDIM + d;

    __shared__ float sB[CHUNK][DSTATE];
    __shared__ float sR[CHUNK][NHEADS];
    for (int t = threadIdx.x; t < CHUNK * DSTATE; t += 128) {
        int tt = t >> 4, n = t & 15;
        size_t pm = (size_t)(b * SEQ + c * CHUNK + tt) * NPROJ;
        sB[tt][n] = g_proj[pm + NHEADS + n];
        sR[tt][n] = g_proj[pm + n];
    }
    __syncthreads();

    float w[NHEADS];
#pragma unroll
    for (int hh = 0; hh < NHEADS; hh++) w[hh] = W_dt[(size_t)hh * DINNER + i];
    const float bd = b_dt[i];
    const float Ah = -expf(A_log[h]);
    const float4 cw = *(const float4*)(conv_w + (size_t)i * 4);
    const float cb = conv_b[i];

    const int mbase = b * SEQ + c * CHUNK;
    float x3 = 0.f, x2 = 0.f, x1 = 0.f;
    if (c > 0) {
        x3 = g_xz[(size_t)(mbase - 3) * ROWW + i];
        x2 = g_xz[(size_t)(mbase - 2) * ROWW + i];
        x1 = g_xz[(size_t)(mbase - 1) * ROWW + i];
    }

    float s[DSTATE];
#pragma unroll
    for (int n = 0; n < DSTATE; n++) s[n] = 0.f;
    float cum = 0.f;
    float P   = 1.f;

    for (int tt = 0; tt < CHUNK; tt++) {
        float raw = bd;
#pragma unroll
        for (int hh = 0; hh < NHEADS; hh++) raw = fmaf(sR[tt][hh], w[hh], raw);
        float dtv = softplus_acc(raw);
        cum += dtv;
        float a = expf(Ah * cum);
        P *= a;

        float x0 = g_xz[(size_t)(mbase + tt) * ROWW + i];
        float cv = cb;
        cv = fmaf(cw.x, x3, cv);
        cv = fmaf(cw.y, x2, cv);
        cv = fmaf(cw.z, x1, cv);
        cv = fmaf(cw.w, x0, cv);
        float xc = silu_acc(cv);
        x3 = x2; x2 = x1; x1 = x0;

        float u = dtv * xc;
#pragma unroll
        for (int n = 0; n < DSTATE; n++)
            s[n] = fmaf(s[n], a, u * sB[tt][n]);
    }
    const int base = ((b * NHEADS + h) * NCHUNK + c) * HDIM + d;
    g_P[base] = P;
#pragma unroll
    for (int n = 0; n < DSTATE; n++) g_S[(size_t)base * DSTATE + n] = s[n];
}

// ---------------------------------------------------------------------------
// Pass 2: stitch across chunks
// ---------------------------------------------------------------------------
__global__ __launch_bounds__(128) void scan_pass2()
{
    int idx = blockIdx.x * 128 + threadIdx.x;
    int d   = idx & (HDIM - 1);
    int bh  = idx >> 7;

    float s[DSTATE];
#pragma unroll
    for (int n = 0; n < DSTATE; n++) s[n] = 0.f;

    for (int c = 0; c < NCHUNK; c++) {
        int base = (bh * NCHUNK + c) * HDIM + d;
        float Pv = g_P[base];
#pragma unroll
        for (int n = 0; n < DSTATE; n++) {
            float Sl = g_S[(size_t)base * DSTATE + n];
            g_S[(size_t)base * DSTATE + n] = s[n];
            s[n] = fmaf(Pv, s[n], Sl);
        }
    }
}

// ---------------------------------------------------------------------------
// Pass 3: replay (rolling conv) + y = C.s + D*x, gate with silu(z) -> g_y raw
// ---------------------------------------------------------------------------
__global__ __launch_bounds__(128) void scan_pass3(
    const float* __restrict__ W_dt, const float* __restrict__ b_dt,
    const float* __restrict__ A_log, const float* __restrict__ D_skip,
    const float* __restrict__ conv_w, const float* __restrict__ conv_b)
{
    const int blk = blockIdx.x;
    const int c   = blk & (NCHUNK - 1);
    const int h   = (blk >> 6) & (NHEADS - 1);
    const int b   = blk >> 10;
    const int d   = threadIdx.x;
    const int i   = h * HDIM + d;

    __shared__ float sB[CHUNK][DSTATE];
    __shared__ float sC[CHUNK][DSTATE];
    __shared__ float sR[CHUNK][NHEADS];
    for (int t = threadIdx.x; t < CHUNK * DSTATE; t += 128) {
        int tt = t >> 4, n = t & 15;
        size_t pm = (size_t)(b * SEQ + c * CHUNK + tt) * NPROJ;
        sB[tt][n] = g_proj[pm + NHEADS + n];
        sC[tt][n] = g_proj[pm + NHEADS + DSTATE + n];
        sR[tt][n] = g_proj[pm + n];
    }
    __syncthreads();

    float w[NHEADS];
#pragma unroll
    for (int hh = 0; hh < NHEADS; hh++) w[hh] = W_dt[(size_t)hh * DINNER + i];
    const float bd = b_dt[i];
    const float Ah = -expf(A_log[h]);
    const float Dh = D_skip[h];
    const float4 cw = *(const float4*)(conv_w + (size_t)i * 4);
    const float cb = conv_b[i];

    const int base = ((b * NHEADS + h) * NCHUNK + c) * HDIM + d;
    float s[DSTATE];
#pragma unroll
    for (int n = 0; n < DSTATE; n++) s[n] = g_S[(size_t)base * DSTATE + n];

    const int mbase = b * SEQ + c * CHUNK;
    float x3 = 0.f, x2 = 0.f, x1 = 0.f;
    if (c > 0) {
        x3 = g_xz[(size_t)(mbase - 3) * ROWW + i];
        x2 = g_xz[(size_t)(mbase - 2) * ROWW + i];
        x1 = g_xz[(size_t)(mbase - 1) * ROWW + i];
    }

    float cum = 0.f;
    for (int tt = 0; tt < CHUNK; tt++) {
        float raw = bd;
#pragma unroll
        for (int hh = 0; hh < NHEADS; hh++) raw = fmaf(sR[tt][hh], w[hh], raw);
        float dtv = softplus_acc(raw);
        cum += dtv;
        float a = expf(Ah * cum);

        const size_t rowoff = (size_t)(mbase + tt) * ROWW;
        float x0 = g_xz[rowoff + i];
        float cv = cb;
        cv = fmaf(cw.x, x3, cv);
        cv = fmaf(cw.y, x2, cv);
        cv = fmaf(cw.z, x1, cv);
        cv = fmaf(cw.w, x0, cv);
        float xc = silu_acc(cv);
        x3 = x2; x2 = x1; x1 = x0;

        float u = dtv * xc;
        float y = 0.f;
#pragma unroll
        for (int n = 0; n < DSTATE; n++) {
            s[n] = fmaf(s[n], a, u * sB[tt][n]);
            y    = fmaf(s[n], sC[tt][n], y);
        }
        y = fmaf(Dh, xc, y);
        float zv = g_xz[rowoff + DINNER + i];
        y *= silu_acc(zv);
        g_y[(size_t)(mbase + tt) * DINNER + i] = y;
    }
}

// ---------------------------------------------------------------------------
// LayerNorm stats only: per-row {mu, rstd} -> g_lnstats.
// ---------------------------------------------------------------------------
__global__ __launch_bounds__(256) void ln_stats_kernel()
{
    __shared__ float sh[8];
    __shared__ float s_mu;
    const int m   = blockIdx.x;
    const int tid = threadIdx.x;
    const float* row = g_y + (size_t)m * DINNER;

    const int i0 = tid * 4;
    float4 a  = *(const float4*)(row + i0);
    float4 b4 = *(const float4*)(row + 1024 + i0);
    float v[8] = {a.x, a.y, a.z, a.w, b4.x, b4.y, b4.z, b4.w};

    float sum = 0.f;
#pragma unroll
    for (int k = 0; k < 8; k++) sum += v[k];
#pragma unroll
    for (int o = 16; o > 0; o >>= 1) sum += __shfl_xor_sync(0xffffffffu, sum, o);
    if ((tid & 31) == 0) sh[tid >> 5] = sum;
    __syncthreads();
    if (tid < 32) {
        float t = (tid < 8) ? sh[tid] : 0.f;
#pragma unroll
        for (int o = 4; o > 0; o >>= 1) t += __shfl_xor_sync(0xffffffffu, t, o);
        if (tid == 0) s_mu = t * (1.f / (float)DINNER);
    }
    __syncthreads();
    const float mu = s_mu;

    float var = 0.f;
#pragma unroll
    for (int k = 0; k < 8; k++) { float dv = v[k] - mu; var = fmaf(dv, dv, var); }
#pragma unroll
    for (int o = 16; o > 0; o >>= 1) var += __shfl_xor_sync(0xffffffffu, var, o);
    __syncthreads();
    if ((tid & 31) == 0) sh[tid >> 5] = var;
    __syncthreads();
    if (tid < 32) {
        float t = (tid < 8) ? sh[tid] : 0.f;
#pragma unroll
        for (int o = 4; o > 0; o >>= 1) t += __shfl_xor_sync(0xffffffffu, t, o);
        if (tid == 0) {
            float rstd = rsqrtf(t * (1.f / (float)DINNER) + LN_EPS);
            g_lnstats[m] = make_float2(mu, rstd);
        }
    }
}

// ---------------------------------------------------------------------------
// kernel_launch
// ---------------------------------------------------------------------------
extern "C" void kernel_launch(void* const* d_in, const int* in_sizes, int n_in,
                              void* d_out, int out_size)
{
    const float* x       = (const float*)d_in[0];
    const float* W_in    = (const float*)d_in[1];
    const float* conv_w  = (const float*)d_in[2];
    const float* conv_b  = (const float*)d_in[3];
    const float* W_xproj = (const float*)d_in[4];
    const float* W_dt    = (const float*)d_in[5];
    const float* b_dt    = (const float*)d_in[6];
    const float* A_log   = (const float*)d_in[7];
    const float* D_skip  = (const float*)d_in[8];
    const float* W_out   = (const float*)d_in[9];
    const float* ln_g    = (const float*)d_in[10];
    const float* ln_b    = (const float*)d_in[11];
    float* out = (float*)d_out;

    float *pxz = nullptr, *py = nullptr;
    cudaGetSymbolAddress((void**)&pxz, g_xz);
    cudaGetSymbolAddress((void**)&py,  g_y);

    // 1) xz = x @ W_in   [8192,1024]x[1024,4096]
    dim3 g1(2 * DINNER / 128, M_ROWS / 128);
    gemm_tf32<<<g1, 256>>>(x, W_in, pxz, M_ROWS, 2 * DINNER, DMODEL);

    // 2) proj = silu(conv(xe)) @ W_xproj  (conv fused; g_xc eliminated)
    proj_conv_kernel<<<M_ROWS / 32, 256>>>(W_xproj, conv_w, conv_b);

    // 3) chunked scan with rolling-window conv
    scan_pass1<<<BATCH * NHEADS * NCHUNK, 128>>>(W_dt, b_dt, A_log, conv_w, conv_b);
    scan_pass2<<<(BATCH * NHEADS * HDIM) / 128, 128>>>();
    scan_pass3<<<BATCH * NHEADS * NCHUNK, 128>>>(W_dt, b_dt, A_log, D_skip, conv_w, conv_b);

    // 4) LN stats (mu/rstd); normalization fused into GEMM2 staging
    ln_stats_kernel<<<M_ROWS, 256>>>();

    // 5) out = LN(y) @ W_out   [8192,2048]x[2048,1024]
    dim3 g2(DMODEL / 128, M_ROWS / 128);
    gemm_tf32_ln<<<g2, 256>>>(py, W_out, out, M_ROWS, DMODEL, DINNER, ln_g, ln_b);
}

// round 8
// speedup vs baseline: 1.0409x; 1.0409x over previous
#include <cuda_runtime.h>
#include <math.h>
#include <stdint.h>

// ---------------------------------------------------------------------------
// Problem constants
// ---------------------------------------------------------------------------
#define BATCH   2
#define SEQ     4096
#define DMODEL  1024
#define DINNER  2048
#define NHEADS  16
#define HDIM    128
#define DSTATE  16
#define DCONV   4
#define CHUNK   64
#define NCHUNK  (SEQ / CHUNK)      // 64
#define M_ROWS  (BATCH * SEQ)      // 8192
#define NPROJ   (NHEADS + 2*DSTATE) // 48
#define ROWW    (2 * DINNER)        // g_xz row width
#define LN_EPS  1e-5f

// ---------------------------------------------------------------------------
// Scratch (static device globals -- no allocation allowed)
// ---------------------------------------------------------------------------
__device__ float  g_xz[(size_t)M_ROWS * ROWW];          // [xe | z]
__device__ float  g_proj[(size_t)M_ROWS * NPROJ];       // dt_raw | B | C
__device__ float  g_y[(size_t)M_ROWS * DINNER];         // raw gated y (pre-LN)
__device__ float  g_S[(size_t)BATCH*NHEADS*NCHUNK*HDIM*DSTATE];
__device__ float  g_P[(size_t)BATCH*NHEADS*NCHUNK*HDIM];
__device__ float2 g_lnstats[M_ROWS];                    // {mu, rstd} per row

// ---------------------------------------------------------------------------
// Helpers (IEEE-accurate transcendentals; tf32 GEMMs own the error budget)
// ---------------------------------------------------------------------------
__device__ __forceinline__ uint32_t tf32_rn(float x) {
    uint32_t r;
    asm("cvt.rna.tf32.f32 %0, %1;" : "=r"(r) : "f"(x));
    return r;
}
__device__ __forceinline__ uint4 cvt4(float4 v) {
    uint4 u;
    u.x = tf32_rn(v.x); u.y = tf32_rn(v.y); u.z = tf32_rn(v.z); u.w = tf32_rn(v.w);
    return u;
}
__device__ __forceinline__ void mma_tf32(float* c, const uint32_t* a, const uint32_t* b) {
    asm volatile(
        "mma.sync.aligned.m16n8k8.row.col.f32.tf32.tf32.f32 "
        "{%0,%1,%2,%3},{%4,%5,%6,%7},{%8,%9},{%0,%1,%2,%3};"
        : "+f"(c[0]), "+f"(c[1]), "+f"(c[2]), "+f"(c[3])
        : "r"(a[0]), "r"(a[1]), "r"(a[2]), "r"(a[3]), "r"(b[0]), "r"(b[1]));
}
__device__ __forceinline__ float softplus_acc(float x) {
    return (x > 20.f) ? x : log1pf(expf(x));
}
__device__ __forceinline__ float silu_acc(float v) {
    return v / (1.f + expf(-v));
}
__device__ __forceinline__ float4 ln_apply(float4 v, float mu, float rs,
                                           const float* __restrict__ g,
                                           const float* __restrict__ b, int col) {
    float4 gg = *(const float4*)(g + col);
    float4 bb = *(const float4*)(b + col);
    v.x = (v.x - mu) * rs * gg.x + bb.x;
    v.y = (v.y - mu) * rs * gg.y + bb.y;
    v.z = (v.z - mu) * rs * gg.z + bb.z;
    v.w = (v.w - mu) * rs * gg.w + bb.w;
    return v;
}

// ---------------------------------------------------------------------------
// TF32 tensor-core GEMM (R2/R6 configuration -- measured good):
// 256 threads, BM=BN=128, BK=16, warp tile 64x32, double-buffered smem.
// ---------------------------------------------------------------------------
__global__ __launch_bounds__(256, 2) void gemm_tf32(
    const float* __restrict__ A, const float* __restrict__ B,
    float* __restrict__ C, int M, int N, int K)
{
    __shared__ uint32_t As[2][128][20];
    __shared__ uint32_t Bs[2][16][136];

    const int tid  = threadIdx.x;
    const int warp = tid >> 5, lane = tid & 31;
    const int g    = lane >> 2, q = lane & 3;
    const int wm   = (warp & 1) * 64;
    const int wn   = (warp >> 1) * 32;
    const int m0   = blockIdx.y * 128;
    const int n0   = blockIdx.x * 128;

    const int ar = tid >> 1;
    const int ac = (tid & 1) * 8;
    const int br = tid >> 4;
    const int bc = (tid & 15) * 8;

    const float* Aptr = A + (size_t)(m0 + ar) * K + ac;
    const float* Bptr = B + (size_t)br * N + n0 + bc;

    float acc[4][4][4];
#pragma unroll
    for (int i = 0; i < 4; i++)
#pragma unroll
        for (int j = 0; j < 4; j++)
#pragma unroll
            for (int k = 0; k < 4; k++) acc[i][j][k] = 0.f;

    {
        float4 a0 = *(const float4*)(Aptr);
        float4 a1 = *(const float4*)(Aptr + 4);
        float4 b0 = *(const float4*)(Bptr);
        float4 b1 = *(const float4*)(Bptr + 4);
        *(uint4*)&As[0][ar][ac]     = cvt4(a0);
        *(uint4*)&As[0][ar][ac + 4] = cvt4(a1);
        *(uint4*)&Bs[0][br][bc]     = cvt4(b0);
        *(uint4*)&Bs[0][br][bc + 4] = cvt4(b1);
    }
    __syncthreads();

    const int nk = K >> 4;
    for (int kt = 0; kt < nk; kt++) {
        const int cur = kt & 1;

        float4 na0, na1, nb0, nb1;
        if (kt + 1 < nk) {
            const float* Ap = Aptr + (kt + 1) * 16;
            const float* Bp = Bptr + (size_t)(kt + 1) * 16 * N;
            na0 = *(const float4*)(Ap);
            na1 = *(const float4*)(Ap + 4);
            nb0 = *(const float4*)(Bp);
            nb1 = *(const float4*)(Bp + 4);
        }

#pragma unroll
        for (int ks = 0; ks < 2; ks++) {
            uint32_t af[4][4], bf[4][2];
            const int kk = ks * 8 + q;
#pragma unroll
            for (int tm = 0; tm < 4; tm++) {
                const int r = wm + tm * 16 + g;
                af[tm][0] = As[cur][r][kk];
                af[tm][1] = As[cur][r + 8][kk];
                af[tm][2] = As[cur][r][kk + 4];
                af[tm][3] = As[cur][r + 8][kk + 4];
            }
#pragma unroll
            for (int tn = 0; tn < 4; tn++) {
                const int n = wn + tn * 8 + g;
                bf[tn][0] = Bs[cur][kk][n];
                bf[tn][1] = Bs[cur][kk + 4][n];
            }
#pragma unroll
            for (int tm = 0; tm < 4; tm++)
#pragma unroll
                for (int tn = 0; tn < 4; tn++)
                    mma_tf32(acc[tm][tn], af[tm], bf[tn]);
        }

        if (kt + 1 < nk) {
            const int nxt = cur ^ 1;
            *(uint4*)&As[nxt][ar][ac]     = cvt4(na0);
            *(uint4*)&As[nxt][ar][ac + 4] = cvt4(na1);
            *(uint4*)&Bs[nxt][br][bc]     = cvt4(nb0);
            *(uint4*)&Bs[nxt][br][bc + 4] = cvt4(nb1);
        }
        __syncthreads();
    }

#pragma unroll
    for (int tm = 0; tm < 4; tm++) {
        const int row = m0 + wm + tm * 16 + g;
#pragma unroll
        for (int tn = 0; tn < 4; tn++) {
            const int col = n0 + wn + tn * 8 + 2 * q;
            *(float2*)&C[(size_t)row * N + col] =
                make_float2(acc[tm][tn][0], acc[tm][tn][1]);
            *(float2*)&C[(size_t)(row + 8) * N + col] =
                make_float2(acc[tm][tn][2], acc[tm][tn][3]);
        }
    }
}

// ---------------------------------------------------------------------------
// GEMM2 variant: applies LayerNorm to A rows during staging.
// ---------------------------------------------------------------------------
__global__ __launch_bounds__(256, 2) void gemm_tf32_ln(
    const float* __restrict__ A, const float* __restrict__ B,
    float* __restrict__ C, int M, int N, int K,
    const float* __restrict__ ln_g, const float* __restrict__ ln_b)
{
    __shared__ uint32_t As[2][128][20];
    __shared__ uint32_t Bs[2][16][136];

    const int tid  = threadIdx.x;
    const int warp = tid >> 5, lane = tid & 31;
    const int g    = lane >> 2, q = lane & 3;
    const int wm   = (warp & 1) * 64;
    const int wn   = (warp >> 1) * 32;
    const int m0   = blockIdx.y * 128;
    const int n0   = blockIdx.x * 128;

    const int ar = tid >> 1;
    const int ac = (tid & 1) * 8;
    const int br = tid >> 4;
    const int bc = (tid & 15) * 8;

    const float* Aptr = A + (size_t)(m0 + ar) * K + ac;
    const float* Bptr = B + (size_t)br * N + n0 + bc;

    const float2 st = g_lnstats[m0 + ar];
    const float mu = st.x, rs = st.y;

    float acc[4][4][4];
#pragma unroll
    for (int i = 0; i < 4; i++)
#pragma unroll
        for (int j = 0; j < 4; j++)
#pragma unroll
            for (int k = 0; k < 4; k++) acc[i][j][k] = 0.f;

    {
        float4 a0 = ln_apply(*(const float4*)(Aptr),     mu, rs, ln_g, ln_b, ac);
        float4 a1 = ln_apply(*(const float4*)(Aptr + 4), mu, rs, ln_g, ln_b, ac + 4);
        float4 b0 = *(const float4*)(Bptr);
        float4 b1 = *(const float4*)(Bptr + 4);
        *(uint4*)&As[0][ar][ac]     = cvt4(a0);
        *(uint4*)&As[0][ar][ac + 4] = cvt4(a1);
        *(uint4*)&Bs[0][br][bc]     = cvt4(b0);
        *(uint4*)&Bs[0][br][bc + 4] = cvt4(b1);
    }
    __syncthreads();

    const int nk = K >> 4;
    for (int kt = 0; kt < nk; kt++) {
        const int cur = kt & 1;

        float4 na0, na1, nb0, nb1;
        if (kt + 1 < nk) {
            const float* Ap = Aptr + (kt + 1) * 16;
            const float* Bp = Bptr + (size_t)(kt + 1) * 16 * N;
            const int colb = (kt + 1) * 16 + ac;
            na0 = ln_apply(*(const float4*)(Ap),     mu, rs, ln_g, ln_b, colb);
            na1 = ln_apply(*(const float4*)(Ap + 4), mu, rs, ln_g, ln_b, colb + 4);
            nb0 = *(const float4*)(Bp);
            nb1 = *(const float4*)(Bp + 4);
        }

#pragma unroll
        for (int ks = 0; ks < 2; ks++) {
            uint32_t af[4][4], bf[4][2];
            const int kk = ks * 8 + q;
#pragma unroll
            for (int tm = 0; tm < 4; tm++) {
                const int r = wm + tm * 16 + g;
                af[tm][0] = As[cur][r][kk];
                af[tm][1] = As[cur][r + 8][kk];
                af[tm][2] = As[cur][r][kk + 4];
                af[tm][3] = As[cur][r + 8][kk + 4];
            }
#pragma unroll
            for (int tn = 0; tn < 4; tn++) {
                const int n = wn + tn * 8 + g;
                bf[tn][0] = Bs[cur][kk][n];
                bf[tn][1] = Bs[cur][kk + 4][n];
            }
#pragma unroll
            for (int tm = 0; tm < 4; tm++)
#pragma unroll
                for (int tn = 0; tn < 4; tn++)
                    mma_tf32(acc[tm][tn], af[tm], bf[tn]);
        }

        if (kt + 1 < nk) {
            const int nxt = cur ^ 1;
            *(uint4*)&As[nxt][ar][ac]     = cvt4(na0);
            *(uint4*)&As[nxt][ar][ac + 4] = cvt4(na1);
            *(uint4*)&Bs[nxt][br][bc]     = cvt4(nb0);
            *(uint4*)&Bs[nxt][br][bc + 4] = cvt4(nb1);
        }
        __syncthreads();
    }

#pragma unroll
    for (int tm = 0; tm < 4; tm++) {
        const int row = m0 + wm + tm * 16 + g;
#pragma unroll
        for (int tn = 0; tn < 4; tn++) {
            const int col = n0 + wn + tn * 8 + 2 * q;
            *(float2*)&C[(size_t)row * N + col] =
                make_float2(acc[tm][tn][0], acc[tm][tn][1]);
            *(float2*)&C[(size_t)(row + 8) * N + col] =
                make_float2(acc[tm][tn][2], acc[tm][tn][3]);
        }
    }
}

// ---------------------------------------------------------------------------
// proj + fused depthwise conv + silu.
// ---------------------------------------------------------------------------
__global__ __launch_bounds__(256) void proj_conv_kernel(
    const float* __restrict__ W_xproj, const float* __restrict__ conv_w,
    const float* __restrict__ conv_b)
{
    __shared__ float xr[35][64];
    __shared__ float ws[64][NPROJ];
    __shared__ float xs[32][64];
    const int tid = threadIdx.x;
    const int m0  = blockIdx.x * 32;
    const bool seqstart = ((m0 & (SEQ - 1)) == 0);

    float acc[6];
#pragma unroll
    for (int o = 0; o < 6; o++) acc[o] = 0.f;

    for (int k0 = 0; k0 < DINNER; k0 += 64) {
        for (int t = tid; t < 35 * 64; t += 256) {
            int rr = t >> 6, cc = t & 63;
            float v = 0.f;
            if (!(seqstart && rr < 3))
                v = g_xz[(size_t)(m0 - 3 + rr) * ROWW + k0 + cc];
            xr[rr][cc] = v;
        }
        for (int t = tid; t < 64 * NPROJ; t += 256) {
            int kk = t / NPROJ;
            int j  = t - kk * NPROJ;
            ws[kk][j] = W_xproj[(size_t)(k0 + kk) * NPROJ + j];
        }
        __syncthreads();

        for (int t = tid; t < 32 * 64; t += 256) {
            int r  = t >> 6, cc = t & 63;
            int ch = k0 + cc;
            float4 wv = *(const float4*)(conv_w + (size_t)ch * 4);
            float a = conv_b[ch];
            a = fmaf(wv.x, xr[r][cc],     a);
            a = fmaf(wv.y, xr[r + 1][cc], a);
            a = fmaf(wv.z, xr[r + 2][cc], a);
            a = fmaf(wv.w, xr[r + 3][cc], a);
            xs[r][cc] = silu_acc(a);
        }
        __syncthreads();

#pragma unroll
        for (int o = 0; o < 6; o++) {
            int oi = o * 256 + tid;
            int r  = oi / NPROJ;
            int j  = oi - r * NPROJ;
            float a = acc[o];
#pragma unroll 8
            for (int kk = 0; kk < 64; kk++)
                a = fmaf(xs[r][kk], ws[kk][j], a);
            acc[o] = a;
        }
        __syncthreads();
    }
#pragma unroll
    for (int o = 0; o < 6; o++) {
        int oi = o * 256 + tid;
        int r  = oi / NPROJ;
        int j  = oi - r * NPROJ;
        g_proj[(size_t)(m0 + r) * NPROJ + j] = acc[o];
    }
}

// ---------------------------------------------------------------------------
// Chunked scan, pass 1: rolling-window conv+silu, dt/decay on the fly.
// g_P is the PRODUCT of all 64 per-step decays.
// ---------------------------------------------------------------------------
__global__ __launch_bounds__(128) void scan_pass1(
    const float* __restrict__ W_dt, const float* __restrict__ b_dt,
    const float* __restrict__ A_log, const float* __restrict__ conv_w,
    const float* __restrict__ conv_b)
{
    const int blk = blockIdx.x;
    const int c   = blk & (NCHUNK - 1);
    const int h   = (blk >> 6) & (NHEADS - 1);
    const int b   = blk >> 10;
    const int d   = threadIdx.x;
    const int i   = h * HDIM + d;

    __shared__ float sB[CHUNK][DSTATE];
    __shared__ float sR[CHUNK][NHEADS];
    for (int t = threadIdx.x; t < CHUNK * DSTATE; t += 128) {
        int tt = t >> 4, n = t & 15;
        size_t pm = (size_t)(b * SEQ + c * CHUNK + tt) * NPROJ;
        sB[tt][n] = g_proj[pm + NHEADS + n];
        sR[tt][n] = g_proj[pm + n];
    }
    __syncthreads();

    float w[NHEADS];
#pragma unroll
    for (int hh = 0; hh < NHEADS; hh++) w[hh] = W_dt[(size_t)hh * DINNER + i];
    const float bd = b_dt[i];
    const float Ah = -expf(A_log[h]);
    const float4 cw = *(const float4*)(conv_w + (size_t)i * 4);
    const float cb = conv_b[i];

    const int mbase = b * SEQ + c * CHUNK;
    float x3 = 0.f, x2 = 0.f, x1 = 0.f;
    if (c > 0) {
        x3 = g_xz[(size_t)(mbase - 3) * ROWW + i];
        x2 = g_xz[(size_t)(mbase - 2) * ROWW + i];
        x1 = g_xz[(size_t)(mbase - 1) * ROWW + i];
    }

    float s[DSTATE];
#pragma unroll
    for (int n = 0; n < DSTATE; n++) s[n] = 0.f;
    float cum = 0.f;
    float P   = 1.f;

    for (int tt = 0; tt < CHUNK; tt++) {
        float raw = bd;
#pragma unroll
        for (int hh = 0; hh < NHEADS; hh++) raw = fmaf(sR[tt][hh], w[hh], raw);
        float dtv = softplus_acc(raw);
        cum += dtv;
        float a = expf(Ah * cum);
        P *= a;

        float x0 = g_xz[(size_t)(mbase + tt) * ROWW + i];
        float cv = cb;
        cv = fmaf(cw.x, x3, cv);
        cv = fmaf(cw.y, x2, cv);
        cv = fmaf(cw.z, x1, cv);
        cv = fmaf(cw.w, x0, cv);
        float xc = silu_acc(cv);
        x3 = x2; x2 = x1; x1 = x0;

        float u = dtv * xc;
#pragma unroll
        for (int n = 0; n < DSTATE; n++)
            s[n] = fmaf(s[n], a, u * sB[tt][n]);
    }
    const int base = ((b * NHEADS + h) * NCHUNK + c) * HDIM + d;
    g_P[base] = P;
#pragma unroll
    for (int n = 0; n < DSTATE; n++) g_S[(size_t)base * DSTATE + n] = s[n];
}

// ---------------------------------------------------------------------------
// Pass 2: stitch across chunks.
// Thread per (b,h,d,n): 65536 threads, fully coalesced g_S, broadcast g_P.
// Same per-element fp32 op order as the old per-(b,h,d) loop -> bit-identical.
// ---------------------------------------------------------------------------
__global__ __launch_bounds__(256) void scan_pass2()
{
    const int idx = blockIdx.x * 256 + threadIdx.x;   // BATCH*NHEADS*HDIM*DSTATE
    const int n   = idx & (DSTATE - 1);
    const int d   = (idx >> 4) & (HDIM - 1);
    const int bh  = idx >> 11;                        // 0..31

    float s = 0.f;
#pragma unroll 4
    for (int c = 0; c < NCHUNK; c++) {
        const int base = (bh * NCHUNK + c) * HDIM + d;
        const float Pv = g_P[base];
        const size_t off = (size_t)base * DSTATE + n;
        float Sl = g_S[off];
        g_S[off] = s;                 // incoming state for chunk c
        s = fmaf(Pv, s, Sl);
    }
}

// ---------------------------------------------------------------------------
// Pass 3: replay (rolling conv) + y = C.s + D*x, gate with silu(z) -> g_y raw
// ---------------------------------------------------------------------------
__global__ __launch_bounds__(128) void scan_pass3(
    const float* __restrict__ W_dt, const float* __restrict__ b_dt,
    const float* __restrict__ A_log, const float* __restrict__ D_skip,
    const float* __restrict__ conv_w, const float* __restrict__ conv_b)
{
    const int blk = blockIdx.x;
    const int c   = blk & (NCHUNK - 1);
    const int h   = (blk >> 6) & (NHEADS - 1);
    const int b   = blk >> 10;
    const int d   = threadIdx.x;
    const int i   = h * HDIM + d;

    __shared__ float sB[CHUNK][DSTATE];
    __shared__ float sC[CHUNK][DSTATE];
    __shared__ float sR[CHUNK][NHEADS];
    for (int t = threadIdx.x; t < CHUNK * DSTATE; t += 128) {
        int tt = t >> 4, n = t & 15;
        size_t pm = (size_t)(b * SEQ + c * CHUNK + tt) * NPROJ;
        sB[tt][n] = g_proj[pm + NHEADS + n];
        sC[tt][n] = g_proj[pm + NHEADS + DSTATE + n];
        sR[tt][n] = g_proj[pm + n];
    }
    __syncthreads();

    float w[NHEADS];
#pragma unroll
    for (int hh = 0; hh < NHEADS; hh++) w[hh] = W_dt[(size_t)hh * DINNER + i];
    const float bd = b_dt[i];
    const float Ah = -expf(A_log[h]);
    const float Dh = D_skip[h];
    const float4 cw = *(const float4*)(conv_w + (size_t)i * 4);
    const float cb = conv_b[i];

    const int base = ((b * NHEADS + h) * NCHUNK + c) * HDIM + d;
    float s[DSTATE];
#pragma unroll
    for (int n = 0; n < DSTATE; n++) s[n] = g_S[(size_t)base * DSTATE + n];

    const int mbase = b * SEQ + c * CHUNK;
    float x3 = 0.f, x2 = 0.f, x1 = 0.f;
    if (c > 0) {
        x3 = g_xz[(size_t)(mbase - 3) * ROWW + i];
        x2 = g_xz[(size_t)(mbase - 2) * ROWW + i];
        x1 = g_xz[(size_t)(mbase - 1) * ROWW + i];
    }

    float cum = 0.f;
    for (int tt = 0; tt < CHUNK; tt++) {
        float raw = bd;
#pragma unroll
        for (int hh = 0; hh < NHEADS; hh++) raw = fmaf(sR[tt][hh], w[hh], raw);
        float dtv = softplus_acc(raw);
        cum += dtv;
        float a = expf(Ah * cum);

        const size_t rowoff = (size_t)(mbase + tt) * ROWW;
        float x0 = g_xz[rowoff + i];
        float cv = cb;
        cv = fmaf(cw.x, x3, cv);
        cv = fmaf(cw.y, x2, cv);
        cv = fmaf(cw.z, x1, cv);
        cv = fmaf(cw.w, x0, cv);
        float xc = silu_acc(cv);
        x3 = x2; x2 = x1; x1 = x0;

        float u = dtv * xc;
        float y = 0.f;
#pragma unroll
        for (int n = 0; n < DSTATE; n++) {
            s[n] = fmaf(s[n], a, u * sB[tt][n]);
            y    = fmaf(s[n], sC[tt][n], y);
        }
        y = fmaf(Dh, xc, y);
        float zv = g_xz[rowoff + DINNER + i];
        y *= silu_acc(zv);
        g_y[(size_t)(mbase + tt) * DINNER + i] = y;
    }
}

// ---------------------------------------------------------------------------
// LayerNorm stats only: per-row {mu, rstd} -> g_lnstats.
// ---------------------------------------------------------------------------
__global__ __launch_bounds__(256) void ln_stats_kernel()
{
    __shared__ float sh[8];
    __shared__ float s_mu;
    const int m   = blockIdx.x;
    const int tid = threadIdx.x;
    const float* row = g_y + (size_t)m * DINNER;

    const int i0 = tid * 4;
    float4 a  = *(const float4*)(row + i0);
    float4 b4 = *(const float4*)(row + 1024 + i0);
    float v[8] = {a.x, a.y, a.z, a.w, b4.x, b4.y, b4.z, b4.w};

    float sum = 0.f;
#pragma unroll
    for (int k = 0; k < 8; k++) sum += v[k];
#pragma unroll
    for (int o = 16; o > 0; o >>= 1) sum += __shfl_xor_sync(0xffffffffu, sum, o);
    if ((tid & 31) == 0) sh[tid >> 5] = sum;
    __syncthreads();
    if (tid < 32) {
        float t = (tid < 8) ? sh[tid] : 0.f;
#pragma unroll
        for (int o = 4; o > 0; o >>= 1) t += __shfl_xor_sync(0xffffffffu, t, o);
        if (tid == 0) s_mu = t * (1.f / (float)DINNER);
    }
    __syncthreads();
    const float mu = s_mu;

    float var = 0.f;
#pragma unroll
    for (int k = 0; k < 8; k++) { float dv = v[k] - mu; var = fmaf(dv, dv, var); }
#pragma unroll
    for (int o = 16; o > 0; o >>= 1) var += __shfl_xor_sync(0xffffffffu, var, o);
    __syncthreads();
    if ((tid & 31) == 0) sh[tid >> 5] = var;
    __syncthreads();
    if (tid < 32) {
        float t = (tid < 8) ? sh[tid] : 0.f;
#pragma unroll
        for (int o = 4; o > 0; o >>= 1) t += __shfl_xor_sync(0xffffffffu, t, o);
        if (tid == 0) {
            float rstd = rsqrtf(t * (1.f / (float)DINNER) + LN_EPS);
            g_lnstats[m] = make_float2(mu, rstd);
        }
    }
}

// ---------------------------------------------------------------------------
// kernel_launch
// ---------------------------------------------------------------------------
extern "C" void kernel_launch(void* const* d_in, const int* in_sizes, int n_in,
                              void* d_out, int out_size)
{
    const float* x       = (const float*)d_in[0];
    const float* W_in    = (const float*)d_in[1];
    const float* conv_w  = (const float*)d_in[2];
    const float* conv_b  = (const float*)d_in[3];
    const float* W_xproj = (const float*)d_in[4];
    const float* W_dt    = (const float*)d_in[5];
    const float* b_dt    = (const float*)d_in[6];
    const float* A_log   = (const float*)d_in[7];
    const float* D_skip  = (const float*)d_in[8];
    const float* W_out   = (const float*)d_in[9];
    const float* ln_g    = (const float*)d_in[10];
    const float* ln_b    = (const float*)d_in[11];
    float* out = (float*)d_out;

    float *pxz = nullptr, *py = nullptr;
    cudaGetSymbolAddress((void**)&pxz, g_xz);
    cudaGetSymbolAddress((void**)&py,  g_y);

    // 1) xz = x @ W_in   [8192,1024]x[1024,4096]
    dim3 g1(2 * DINNER / 128, M_ROWS / 128);
    gemm_tf32<<<g1, 256>>>(x, W_in, pxz, M_ROWS, 2 * DINNER, DMODEL);

    // 2) proj = silu(conv(xe)) @ W_xproj
    proj_conv_kernel<<<M_ROWS / 32, 256>>>(W_xproj, conv_w, conv_b);

    // 3) chunked scan
    scan_pass1<<<BATCH * NHEADS * NCHUNK, 128>>>(W_dt, b_dt, A_log, conv_w, conv_b);
    scan_pass2<<<(BATCH * NHEADS * HDIM * DSTATE) / 256, 256>>>();
    scan_pass3<<<BATCH * NHEADS * NCHUNK, 128>>>(W_dt, b_dt, A_log, D_skip, conv_w, conv_b);

    // 4) LN stats; normalization fused into GEMM2 staging
    ln_stats_kernel<<<M_ROWS, 256>>>();

    // 5) out = LN(y) @ W_out   [8192,2048]x[2048,1024]
    dim3 g2(DMODEL / 128, M_ROWS / 128);
    gemm_tf32_ln<<<g2, 256>>>(py, W_out, out, M_ROWS, DMODEL, DINNER, ln_g, ln_b);
}

// round 9
// speedup vs baseline: 1.0463x; 1.0052x over previous
#include <cuda_runtime.h>
#include <math.h>
#include <stdint.h>

// ---------------------------------------------------------------------------
// Problem constants
// ---------------------------------------------------------------------------
#define BATCH   2
#define SEQ     4096
#define DMODEL  1024
#define DINNER  2048
#define NHEADS  16
#define HDIM    128
#define DSTATE  16
#define DCONV   4
#define CHUNK   64
#define NCHUNK  (SEQ / CHUNK)      // 64
#define M_ROWS  (BATCH * SEQ)      // 8192
#define NPROJ   (NHEADS + 2*DSTATE) // 48
#define ROWW    (2 * DINNER)        // g_xz row width
#define LN_EPS  1e-5f

// ---------------------------------------------------------------------------
// Scratch (static device globals -- no allocation allowed)
// ---------------------------------------------------------------------------
__device__ float  g_xz[(size_t)M_ROWS * ROWW];          // [xe | z]
__device__ float  g_proj[(size_t)M_ROWS * NPROJ];       // dt_raw | B | C
__device__ float  g_y[(size_t)M_ROWS * DINNER];         // raw gated y (pre-LN)
__device__ float  g_S[(size_t)BATCH*NHEADS*NCHUNK*HDIM*DSTATE];   // chunk-local states
__device__ float  g_Sin[(size_t)BATCH*NHEADS*NCHUNK*HDIM*DSTATE]; // incoming states
__device__ float  g_P[(size_t)BATCH*NHEADS*NCHUNK*HDIM];
__device__ float2 g_lnstats[M_ROWS];                    // {mu, rstd} per row

// ---------------------------------------------------------------------------
// Helpers (IEEE-accurate transcendentals; tf32 GEMMs own the error budget)
// ---------------------------------------------------------------------------
__device__ __forceinline__ uint32_t tf32_rn(float x) {
    uint32_t r;
    asm("cvt.rna.tf32.f32 %0, %1;" : "=r"(r) : "f"(x));
    return r;
}
__device__ __forceinline__ uint4 cvt4(float4 v) {
    uint4 u;
    u.x = tf32_rn(v.x); u.y = tf32_rn(v.y); u.z = tf32_rn(v.z); u.w = tf32_rn(v.w);
    return u;
}
__device__ __forceinline__ void mma_tf32(float* c, const uint32_t* a, const uint32_t* b) {
    asm volatile(
        "mma.sync.aligned.m16n8k8.row.col.f32.tf32.tf32.f32 "
        "{%0,%1,%2,%3},{%4,%5,%6,%7},{%8,%9},{%0,%1,%2,%3};"
        : "+f"(c[0]), "+f"(c[1]), "+f"(c[2]), "+f"(c[3])
        : "r"(a[0]), "r"(a[1]), "r"(a[2]), "r"(a[3]), "r"(b[0]), "r"(b[1]));
}
__device__ __forceinline__ float softplus_acc(float x) {
    return (x > 20.f) ? x : log1pf(expf(x));
}
__device__ __forceinline__ float silu_acc(float v) {
    return v / (1.f + expf(-v));
}
__device__ __forceinline__ float4 ln_apply(float4 v, float mu, float rs,
                                           const float* __restrict__ g,
                                           const float* __restrict__ b, int col) {
    float4 gg = *(const float4*)(g + col);
    float4 bb = *(const float4*)(b + col);
    v.x = (v.x - mu) * rs * gg.x + bb.x;
    v.y = (v.y - mu) * rs * gg.y + bb.y;
    v.z = (v.z - mu) * rs * gg.z + bb.z;
    v.w = (v.w - mu) * rs * gg.w + bb.w;
    return v;
}

// ---------------------------------------------------------------------------
// TF32 tensor-core GEMM (R2/R6 configuration -- measured good):
// 256 threads, BM=BN=128, BK=16, warp tile 64x32, double-buffered smem.
// ---------------------------------------------------------------------------
__global__ __launch_bounds__(256, 2) void gemm_tf32(
    const float* __restrict__ A, const float* __restrict__ B,
    float* __restrict__ C, int M, int N, int K)
{
    __shared__ uint32_t As[2][128][20];
    __shared__ uint32_t Bs[2][16][136];

    const int tid  = threadIdx.x;
    const int warp = tid >> 5, lane = tid & 31;
    const int g    = lane >> 2, q = lane & 3;
    const int wm   = (warp & 1) * 64;
    const int wn   = (warp >> 1) * 32;
    const int m0   = blockIdx.y * 128;
    const int n0   = blockIdx.x * 128;

    const int ar = tid >> 1;
    const int ac = (tid & 1) * 8;
    const int br = tid >> 4;
    const int bc = (tid & 15) * 8;

    const float* Aptr = A + (size_t)(m0 + ar) * K + ac;
    const float* Bptr = B + (size_t)br * N + n0 + bc;

    float acc[4][4][4];
#pragma unroll
    for (int i = 0; i < 4; i++)
#pragma unroll
        for (int j = 0; j < 4; j++)
#pragma unroll
            for (int k = 0; k < 4; k++) acc[i][j][k] = 0.f;

    {
        float4 a0 = *(const float4*)(Aptr);
        float4 a1 = *(const float4*)(Aptr + 4);
        float4 b0 = *(const float4*)(Bptr);
        float4 b1 = *(const float4*)(Bptr + 4);
        *(uint4*)&As[0][ar][ac]     = cvt4(a0);
        *(uint4*)&As[0][ar][ac + 4] = cvt4(a1);
        *(uint4*)&Bs[0][br][bc]     = cvt4(b0);
        *(uint4*)&Bs[0][br][bc + 4] = cvt4(b1);
    }
    __syncthreads();

    const int nk = K >> 4;
    for (int kt = 0; kt < nk; kt++) {
        const int cur = kt & 1;

        float4 na0, na1, nb0, nb1;
        if (kt + 1 < nk) {
            const float* Ap = Aptr + (kt + 1) * 16;
            const float* Bp = Bptr + (size_t)(kt + 1) * 16 * N;
            na0 = *(const float4*)(Ap);
            na1 = *(const float4*)(Ap + 4);
            nb0 = *(const float4*)(Bp);
            nb1 = *(const float4*)(Bp + 4);
        }

#pragma unroll
        for (int ks = 0; ks < 2; ks++) {
            uint32_t af[4][4], bf[4][2];
            const int kk = ks * 8 + q;
#pragma unroll
            for (int tm = 0; tm < 4; tm++) {
                const int r = wm + tm * 16 + g;
                af[tm][0] = As[cur][r][kk];
                af[tm][1] = As[cur][r + 8][kk];
                af[tm][2] = As[cur][r][kk + 4];
                af[tm][3] = As[cur][r + 8][kk + 4];
            }
#pragma unroll
            for (int tn = 0; tn < 4; tn++) {
                const int n = wn + tn * 8 + g;
                bf[tn][0] = Bs[cur][kk][n];
                bf[tn][1] = Bs[cur][kk + 4][n];
            }
#pragma unroll
            for (int tm = 0; tm < 4; tm++)
#pragma unroll
                for (int tn = 0; tn < 4; tn++)
                    mma_tf32(acc[tm][tn], af[tm], bf[tn]);
        }

        if (kt + 1 < nk) {
            const int nxt = cur ^ 1;
            *(uint4*)&As[nxt][ar][ac]     = cvt4(na0);
            *(uint4*)&As[nxt][ar][ac + 4] = cvt4(na1);
            *(uint4*)&Bs[nxt][br][bc]     = cvt4(nb0);
            *(uint4*)&Bs[nxt][br][bc + 4] = cvt4(nb1);
        }
        __syncthreads();
    }

#pragma unroll
    for (int tm = 0; tm < 4; tm++) {
        const int row = m0 + wm + tm * 16 + g;
#pragma unroll
        for (int tn = 0; tn < 4; tn++) {
            const int col = n0 + wn + tn * 8 + 2 * q;
            *(float2*)&C[(size_t)row * N + col] =
                make_float2(acc[tm][tn][0], acc[tm][tn][1]);
            *(float2*)&C[(size_t)(row + 8) * N + col] =
                make_float2(acc[tm][tn][2], acc[tm][tn][3]);
        }
    }
}

// ---------------------------------------------------------------------------
// GEMM2 variant: applies LayerNorm to A rows during staging.
// ---------------------------------------------------------------------------
__global__ __launch_bounds__(256, 2) void gemm_tf32_ln(
    const float* __restrict__ A, const float* __restrict__ B,
    float* __restrict__ C, int M, int N, int K,
    const float* __restrict__ ln_g, const float* __restrict__ ln_b)
{
    __shared__ uint32_t As[2][128][20];
    __shared__ uint32_t Bs[2][16][136];

    const int tid  = threadIdx.x;
    const int warp = tid >> 5, lane = tid & 31;
    const int g    = lane >> 2, q = lane & 3;
    const int wm   = (warp & 1) * 64;
    const int wn   = (warp >> 1) * 32;
    const int m0   = blockIdx.y * 128;
    const int n0   = blockIdx.x * 128;

    const int ar = tid >> 1;
    const int ac = (tid & 1) * 8;
    const int br = tid >> 4;
    const int bc = (tid & 15) * 8;

    const float* Aptr = A + (size_t)(m0 + ar) * K + ac;
    const float* Bptr = B + (size_t)br * N + n0 + bc;

    const float2 st = g_lnstats[m0 + ar];
    const float mu = st.x, rs = st.y;

    float acc[4][4][4];
#pragma unroll
    for (int i = 0; i < 4; i++)
#pragma unroll
        for (int j = 0; j < 4; j++)
#pragma unroll
            for (int k = 0; k < 4; k++) acc[i][j][k] = 0.f;

    {
        float4 a0 = ln_apply(*(const float4*)(Aptr),     mu, rs, ln_g, ln_b, ac);
        float4 a1 = ln_apply(*(const float4*)(Aptr + 4), mu, rs, ln_g, ln_b, ac + 4);
        float4 b0 = *(const float4*)(Bptr);
        float4 b1 = *(const float4*)(Bptr + 4);
        *(uint4*)&As[0][ar][ac]     = cvt4(a0);
        *(uint4*)&As[0][ar][ac + 4] = cvt4(a1);
        *(uint4*)&Bs[0][br][bc]     = cvt4(b0);
        *(uint4*)&Bs[0][br][bc + 4] = cvt4(b1);
    }
    __syncthreads();

    const int nk = K >> 4;
    for (int kt = 0; kt < nk; kt++) {
        const int cur = kt & 1;

        float4 na0, na1, nb0, nb1;
        if (kt + 1 < nk) {
            const float* Ap = Aptr + (kt + 1) * 16;
            const float* Bp = Bptr + (size_t)(kt + 1) * 16 * N;
            const int colb = (kt + 1) * 16 + ac;
            na0 = ln_apply(*(const float4*)(Ap),     mu, rs, ln_g, ln_b, colb);
            na1 = ln_apply(*(const float4*)(Ap + 4), mu, rs, ln_g, ln_b, colb + 4);
            nb0 = *(const float4*)(Bp);
            nb1 = *(const float4*)(Bp + 4);
        }

#pragma unroll
        for (int ks = 0; ks < 2; ks++) {
            uint32_t af[4][4], bf[4][2];
            const int kk = ks * 8 + q;
#pragma unroll
            for (int tm = 0; tm < 4; tm++) {
                const int r = wm + tm * 16 + g;
                af[tm][0] = As[cur][r][kk];
                af[tm][1] = As[cur][r + 8][kk];
                af[tm][2] = As[cur][r][kk + 4];
                af[tm][3] = As[cur][r + 8][kk + 4];
            }
#pragma unroll
            for (int tn = 0; tn < 4; tn++) {
                const int n = wn + tn * 8 + g;
                bf[tn][0] = Bs[cur][kk][n];
                bf[tn][1] = Bs[cur][kk + 4][n];
            }
#pragma unroll
            for (int tm = 0; tm < 4; tm++)
#pragma unroll
                for (int tn = 0; tn < 4; tn++)
                    mma_tf32(acc[tm][tn], af[tm], bf[tn]);
        }

        if (kt + 1 < nk) {
            const int nxt = cur ^ 1;
            *(uint4*)&As[nxt][ar][ac]     = cvt4(na0);
            *(uint4*)&As[nxt][ar][ac + 4] = cvt4(na1);
            *(uint4*)&Bs[nxt][br][bc]     = cvt4(nb0);
            *(uint4*)&Bs[nxt][br][bc + 4] = cvt4(nb1);
        }
        __syncthreads();
    }

#pragma unroll
    for (int tm = 0; tm < 4; tm++) {
        const int row = m0 + wm + tm * 16 + g;
#pragma unroll
        for (int tn = 0; tn < 4; tn++) {
            const int col = n0 + wn + tn * 8 + 2 * q;
            *(float2*)&C[(size_t)row * N + col] =
                make_float2(acc[tm][tn][0], acc[tm][tn][1]);
            *(float2*)&C[(size_t)(row + 8) * N + col] =
                make_float2(acc[tm][tn][2], acc[tm][tn][3]);
        }
    }
}

// ---------------------------------------------------------------------------
// proj + fused depthwise conv + silu.
// ---------------------------------------------------------------------------
__global__ __launch_bounds__(256) void proj_conv_kernel(
    const float* __restrict__ W_xproj, const float* __restrict__ conv_w,
    const float* __restrict__ conv_b)
{
    __shared__ float xr[35][64];
    __shared__ float ws[64][NPROJ];
    __shared__ float xs[32][64];
    const int tid = threadIdx.x;
    const int m0  = blockIdx.x * 32;
    const bool seqstart = ((m0 & (SEQ - 1)) == 0);

    float acc[6];
#pragma unroll
    for (int o = 0; o < 6; o++) acc[o] = 0.f;

    for (int k0 = 0; k0 < DINNER; k0 += 64) {
        for (int t = tid; t < 35 * 64; t += 256) {
            int rr = t >> 6, cc = t & 63;
            float v = 0.f;
            if (!(seqstart && rr < 3))
                v = g_xz[(size_t)(m0 - 3 + rr) * ROWW + k0 + cc];
            xr[rr][cc] = v;
        }
        for (int t = tid; t < 64 * NPROJ; t += 256) {
            int kk = t / NPROJ;
            int j  = t - kk * NPROJ;
            ws[kk][j] = W_xproj[(size_t)(k0 + kk) * NPROJ + j];
        }
        __syncthreads();

        for (int t = tid; t < 32 * 64; t += 256) {
            int r  = t >> 6, cc = t & 63;
            int ch = k0 + cc;
            float4 wv = *(const float4*)(conv_w + (size_t)ch * 4);
            float a = conv_b[ch];
            a = fmaf(wv.x, xr[r][cc],     a);
            a = fmaf(wv.y, xr[r + 1][cc], a);
            a = fmaf(wv.z, xr[r + 2][cc], a);
            a = fmaf(wv.w, xr[r + 3][cc], a);
            xs[r][cc] = silu_acc(a);
        }
        __syncthreads();

#pragma unroll
        for (int o = 0; o < 6; o++) {
            int oi = o * 256 + tid;
            int r  = oi / NPROJ;
            int j  = oi - r * NPROJ;
            float a = acc[o];
#pragma unroll 8
            for (int kk = 0; kk < 64; kk++)
                a = fmaf(xs[r][kk], ws[kk][j], a);
            acc[o] = a;
        }
        __syncthreads();
    }
#pragma unroll
    for (int o = 0; o < 6; o++) {
        int oi = o * 256 + tid;
        int r  = oi / NPROJ;
        int j  = oi - r * NPROJ;
        g_proj[(size_t)(m0 + r) * NPROJ + j] = acc[o];
    }
}

// ---------------------------------------------------------------------------
// Chunked scan, pass 1: rolling-window conv+silu, dt/decay on the fly.
// g_P is the PRODUCT of all 64 per-step decays.
// ---------------------------------------------------------------------------
__global__ __launch_bounds__(128) void scan_pass1(
    const float* __restrict__ W_dt, const float* __restrict__ b_dt,
    const float* __restrict__ A_log, const float* __restrict__ conv_w,
    const float* __restrict__ conv_b)
{
    const int blk = blockIdx.x;
    const int c   = blk & (NCHUNK - 1);
    const int h   = (blk >> 6) & (NHEADS - 1);
    const int b   = blk >> 10;
    const int d   = threadIdx.x;
    const int i   = h * HDIM + d;

    __shared__ float sB[CHUNK][DSTATE];
    __shared__ float sR[CHUNK][NHEADS];
    for (int t = threadIdx.x; t < CHUNK * DSTATE; t += 128) {
        int tt = t >> 4, n = t & 15;
        size_t pm = (size_t)(b * SEQ + c * CHUNK + tt) * NPROJ;
        sB[tt][n] = g_proj[pm + NHEADS + n];
        sR[tt][n] = g_proj[pm + n];
    }
    __syncthreads();

    float w[NHEADS];
#pragma unroll
    for (int hh = 0; hh < NHEADS; hh++) w[hh] = W_dt[(size_t)hh * DINNER + i];
    const float bd = b_dt[i];
    const float Ah = -expf(A_log[h]);
    const float4 cw = *(const float4*)(conv_w + (size_t)i * 4);
    const float cb = conv_b[i];

    const int mbase = b * SEQ + c * CHUNK;
    float x3 = 0.f, x2 = 0.f, x1 = 0.f;
    if (c > 0) {
        x3 = g_xz[(size_t)(mbase - 3) * ROWW + i];
        x2 = g_xz[(size_t)(mbase - 2) * ROWW + i];
        x1 = g_xz[(size_t)(mbase - 1) * ROWW + i];
    }

    float s[DSTATE];
#pragma unroll
    for (int n = 0; n < DSTATE; n++) s[n] = 0.f;
    float cum = 0.f;
    float P   = 1.f;

    for (int tt = 0; tt < CHUNK; tt++) {
        float raw = bd;
#pragma unroll
        for (int hh = 0; hh < NHEADS; hh++) raw = fmaf(sR[tt][hh], w[hh], raw);
        float dtv = softplus_acc(raw);
        cum += dtv;
        float a = expf(Ah * cum);
        P *= a;

        float x0 = g_xz[(size_t)(mbase + tt) * ROWW + i];
        float cv = cb;
        cv = fmaf(cw.x, x3, cv);
        cv = fmaf(cw.y, x2, cv);
        cv = fmaf(cw.z, x1, cv);
        cv = fmaf(cw.w, x0, cv);
        float xc = silu_acc(cv);
        x3 = x2; x2 = x1; x1 = x0;

        float u = dtv * xc;
#pragma unroll
        for (int n = 0; n < DSTATE; n++)
            s[n] = fmaf(s[n], a, u * sB[tt][n]);
    }
    const int base = ((b * NHEADS + h) * NCHUNK + c) * HDIM + d;
    g_P[base] = P;
#pragma unroll
    for (int n = 0; n < DSTATE; n++) g_S[(size_t)base * DSTATE + n] = s[n];
}

// ---------------------------------------------------------------------------
// Pass 2: stitch across chunks.
// Thread per (b,h,d,n). Writes incoming states to SEPARATE buffer g_Sin so
// the compiler can pipeline g_S/g_P loads across iterations (in-place update
// created a false alias dependency that serialized the loop at DRAM latency).
// ---------------------------------------------------------------------------
__global__ __launch_bounds__(256) void scan_pass2()
{
    const int idx = blockIdx.x * 256 + threadIdx.x;   // BATCH*NHEADS*HDIM*DSTATE
    const int n   = idx & (DSTATE - 1);
    const int d   = (idx >> 4) & (HDIM - 1);
    const int bh  = idx >> 11;                        // 0..31

    float s = 0.f;
#pragma unroll 8
    for (int c = 0; c < NCHUNK; c++) {
        const int base = (bh * NCHUNK + c) * HDIM + d;
        const float Pv = g_P[base];
        const size_t off = (size_t)base * DSTATE + n;
        const float Sl = g_S[off];
        g_Sin[off] = s;               // incoming state for chunk c
        s = fmaf(Pv, s, Sl);
    }
}

// ---------------------------------------------------------------------------
// Pass 3: replay (rolling conv) + y = C.s + D*x, gate with silu(z) -> g_y raw
// ---------------------------------------------------------------------------
__global__ __launch_bounds__(128) void scan_pass3(
    const float* __restrict__ W_dt, const float* __restrict__ b_dt,
    const float* __restrict__ A_log, const float* __restrict__ D_skip,
    const float* __restrict__ conv_w, const float* __restrict__ conv_b)
{
    const int blk = blockIdx.x;
    const int c   = blk & (NCHUNK - 1);
    const int h   = (blk >> 6) & (NHEADS - 1);
    const int b   = blk >> 10;
    const int d   = threadIdx.x;
    const int i   = h * HDIM + d;

    __shared__ float sB[CHUNK][DSTATE];
    __shared__ float sC[CHUNK][DSTATE];
    __shared__ float sR[CHUNK][NHEADS];
    for (int t = threadIdx.x; t < CHUNK * DSTATE; t += 128) {
        int tt = t >> 4, n = t & 15;
        size_t pm = (size_t)(b * SEQ + c * CHUNK + tt) * NPROJ;
        sB[tt][n] = g_proj[pm + NHEADS + n];
        sC[tt][n] = g_proj[pm + NHEADS + DSTATE + n];
        sR[tt][n] = g_proj[pm + n];
    }
    __syncthreads();

    float w[NHEADS];
#pragma unroll
    for (int hh = 0; hh < NHEADS; hh++) w[hh] = W_dt[(size_t)hh * DINNER + i];
    const float bd = b_dt[i];
    const float Ah = -expf(A_log[h]);
    const float Dh = D_skip[h];
    const float4 cw = *(const float4*)(conv_w + (size_t)i * 4);
    const float cb = conv_b[i];

    const int base = ((b * NHEADS + h) * NCHUNK + c) * HDIM + d;
    float s[DSTATE];
#pragma unroll
    for (int n = 0; n < DSTATE; n++) s[n] = g_Sin[(size_t)base * DSTATE + n];

    const int mbase = b * SEQ + c * CHUNK;
    float x3 = 0.f, x2 = 0.f, x1 = 0.f;
    if (c > 0) {
        x3 = g_xz[(size_t)(mbase - 3) * ROWW + i];
        x2 = g_xz[(size_t)(mbase - 2) * ROWW + i];
        x1 = g_xz[(size_t)(mbase - 1) * ROWW + i];
    }

    float cum = 0.f;
    for (int tt = 0; tt < CHUNK; tt++) {
        float raw = bd;
#pragma unroll
        for (int hh = 0; hh < NHEADS; hh++) raw = fmaf(sR[tt][hh], w[hh], raw);
        float dtv = softplus_acc(raw);
        cum += dtv;
        float a = expf(Ah * cum);

        const size_t rowoff = (size_t)(mbase + tt) * ROWW;
        float x0 = g_xz[rowoff + i];
        float cv = cb;
        cv = fmaf(cw.x, x3, cv);
        cv = fmaf(cw.y, x2, cv);
        cv = fmaf(cw.z, x1, cv);
        cv = fmaf(cw.w, x0, cv);
        float xc = silu_acc(cv);
        x3 = x2; x2 = x1; x1 = x0;

        float u = dtv * xc;
        float y = 0.f;
#pragma unroll
        for (int n = 0; n < DSTATE; n++) {
            s[n] = fmaf(s[n], a, u * sB[tt][n]);
            y    = fmaf(s[n], sC[tt][n], y);
        }
        y = fmaf(Dh, xc, y);
        float zv = g_xz[rowoff + DINNER + i];
        y *= silu_acc(zv);
        g_y[(size_t)(mbase + tt) * DINNER + i] = y;
    }
}

// ---------------------------------------------------------------------------
// LayerNorm stats only: per-row {mu, rstd} -> g_lnstats.
// ---------------------------------------------------------------------------
__global__ __launch_bounds__(256) void ln_stats_kernel()
{
    __shared__ float sh[8];
    __shared__ float s_mu;
    const int m   = blockIdx.x;
    const int tid = threadIdx.x;
    const float* row = g_y + (size_t)m * DINNER;

    const int i0 = tid * 4;
    float4 a  = *(const float4*)(row + i0);
    float4 b4 = *(const float4*)(row + 1024 + i0);
    float v[8] = {a.x, a.y, a.z, a.w, b4.x, b4.y, b4.z, b4.w};

    float sum = 0.f;
#pragma unroll
    for (int k = 0; k < 8; k++) sum += v[k];
#pragma unroll
    for (int o = 16; o > 0; o >>= 1) sum += __shfl_xor_sync(0xffffffffu, sum, o);
    if ((tid & 31) == 0) sh[tid >> 5] = sum;
    __syncthreads();
    if (tid < 32) {
        float t = (tid < 8) ? sh[tid] : 0.f;
#pragma unroll
        for (int o = 4; o > 0; o >>= 1) t += __shfl_xor_sync(0xffffffffu, t, o);
        if (tid == 0) s_mu = t * (1.f / (float)DINNER);
    }
    __syncthreads();
    const float mu = s_mu;

    float var = 0.f;
#pragma unroll
    for (int k = 0; k < 8; k++) { float dv = v[k] - mu; var = fmaf(dv, dv, var); }
#pragma unroll
    for (int o = 16; o > 0; o >>= 1) var += __shfl_xor_sync(0xffffffffu, var, o);
    __syncthreads();
    if ((tid & 31) == 0) sh[tid >> 5] = var;
    __syncthreads();
    if (tid < 32) {
        float t = (tid < 8) ? sh[tid] : 0.f;
#pragma unroll
        for (int o = 4; o > 0; o >>= 1) t += __shfl_xor_sync(0xffffffffu, t, o);
        if (tid == 0) {
            float rstd = rsqrtf(t * (1.f / (float)DINNER) + LN_EPS);
            g_lnstats[m] = make_float2(mu, rstd);
        }
    }
}

// ---------------------------------------------------------------------------
// kernel_launch
// ---------------------------------------------------------------------------
extern "C" void kernel_launch(void* const* d_in, const int* in_sizes, int n_in,
                              void* d_out, int out_size)
{
    const float* x       = (const float*)d_in[0];
    const float* W_in    = (const float*)d_in[1];
    const float* conv_w  = (const float*)d_in[2];
    const float* conv_b  = (const float*)d_in[3];
    const float* W_xproj = (const float*)d_in[4];
    const float* W_dt    = (const float*)d_in[5];
    const float* b_dt    = (const float*)d_in[6];
    const float* A_log   = (const float*)d_in[7];
    const float* D_skip  = (const float*)d_in[8];
    const float* W_out   = (const float*)d_in[9];
    const float* ln_g    = (const float*)d_in[10];
    const float* ln_b    = (const float*)d_in[11];
    float* out = (float*)d_out;

    float *pxz = nullptr, *py = nullptr;
    cudaGetSymbolAddress((void**)&pxz, g_xz);
    cudaGetSymbolAddress((void**)&py,  g_y);

    // 1) xz = x @ W_in   [8192,1024]x[1024,4096]
    dim3 g1(2 * DINNER / 128, M_ROWS / 128);
    gemm_tf32<<<g1, 256>>>(x, W_in, pxz, M_ROWS, 2 * DINNER, DMODEL);

    // 2) proj = silu(conv(xe)) @ W_xproj
    proj_conv_kernel<<<M_ROWS / 32, 256>>>(W_xproj, conv_w, conv_b);

    // 3) chunked scan
    scan_pass1<<<BATCH * NHEADS * NCHUNK, 128>>>(W_dt, b_dt, A_log, conv_w, conv_b);
    scan_pass2<<<(BATCH * NHEADS * HDIM * DSTATE) / 256, 256>>>();
    scan_pass3<<<BATCH * NHEADS * NCHUNK, 128>>>(W_dt, b_dt, A_log, D_skip, conv_w, conv_b);

    // 4) LN stats; normalization fused into GEMM2 staging
    ln_stats_kernel<<<M_ROWS, 256>>>();

    // 5) out = LN(y) @ W_out   [8192,2048]x[2048,1024]
    dim3 g2(DMODEL / 128, M_ROWS / 128);
    gemm_tf32_ln<<<g2, 256>>>(py, W_out, out, M_ROWS, DMODEL, DINNER, ln_g, ln_b);
}

// round 10
// speedup vs baseline: 1.0774x; 1.0297x over previous
#include <cuda_runtime.h>
#include <math.h>
#include <stdint.h>

// ---------------------------------------------------------------------------
// Problem constants
// ---------------------------------------------------------------------------
#define BATCH   2
#define SEQ     4096
#define DMODEL  1024
#define DINNER  2048
#define NHEADS  16
#define HDIM    128
#define DSTATE  16
#define DCONV   4
#define CHUNK   64
#define NCHUNK  (SEQ / CHUNK)      // 64
#define M_ROWS  (BATCH * SEQ)      // 8192
#define NPROJ   (NHEADS + 2*DSTATE) // 48
#define ROWW    (2 * DINNER)        // g_xz row width
#define LN_EPS  1e-5f

// Pipelined GEMM config
#define PSTAGES    4
#define AS_STRIDE  20                 // padded row pitch (floats), 80B = 5*16B
#define BS_STRIDE  136                // padded row pitch (floats), 544B = 34*16B
#define AS_STAGE   (128 * AS_STRIDE)  // 2560 floats
#define BS_STAGE   (16 * BS_STRIDE)   // 2176 floats
#define PIPE_SMEM_BYTES ((PSTAGES * (AS_STAGE + BS_STAGE)) * 4)  // 75776 B

// ---------------------------------------------------------------------------
// Scratch (static device globals -- no allocation allowed)
// ---------------------------------------------------------------------------
__device__ float  g_xz[(size_t)M_ROWS * ROWW];          // [xe | z]
__device__ float  g_proj[(size_t)M_ROWS * NPROJ];       // dt_raw | B | C
__device__ float  g_y[(size_t)M_ROWS * DINNER];         // raw gated y (pre-LN)
__device__ float  g_S[(size_t)BATCH*NHEADS*NCHUNK*HDIM*DSTATE];   // chunk-local states
__device__ float  g_Sin[(size_t)BATCH*NHEADS*NCHUNK*HDIM*DSTATE]; // incoming states
__device__ float  g_P[(size_t)BATCH*NHEADS*NCHUNK*HDIM];
__device__ float2 g_lnstats[M_ROWS];                    // {mu, rstd} per row

// ---------------------------------------------------------------------------
// Helpers (IEEE-accurate transcendentals; tf32 GEMMs own the error budget)
// ---------------------------------------------------------------------------
__device__ __forceinline__ uint32_t tf32_rn(float x) {
    uint32_t r;
    asm("cvt.rna.tf32.f32 %0, %1;" : "=r"(r) : "f"(x));
    return r;
}
__device__ __forceinline__ uint4 cvt4(float4 v) {
    uint4 u;
    u.x = tf32_rn(v.x); u.y = tf32_rn(v.y); u.z = tf32_rn(v.z); u.w = tf32_rn(v.w);
    return u;
}
__device__ __forceinline__ void mma_tf32(float* c, const uint32_t* a, const uint32_t* b) {
    asm volatile(
        "mma.sync.aligned.m16n8k8.row.col.f32.tf32.tf32.f32 "
        "{%0,%1,%2,%3},{%4,%5,%6,%7},{%8,%9},{%0,%1,%2,%3};"
        : "+f"(c[0]), "+f"(c[1]), "+f"(c[2]), "+f"(c[3])
        : "r"(a[0]), "r"(a[1]), "r"(a[2]), "r"(a[3]), "r"(b[0]), "r"(b[1]));
}
__device__ __forceinline__ float softplus_acc(float x) {
    return (x > 20.f) ? x : log1pf(expf(x));
}
__device__ __forceinline__ float silu_acc(float v) {
    return v / (1.f + expf(-v));
}
__device__ __forceinline__ float4 ln_apply(float4 v, float mu, float rs,
                                           const float* __restrict__ g,
                                           const float* __restrict__ b, int col) {
    float4 gg = *(const float4*)(g + col);
    float4 bb = *(const float4*)(b + col);
    v.x = (v.x - mu) * rs * gg.x + bb.x;
    v.y = (v.y - mu) * rs * gg.y + bb.y;
    v.z = (v.z - mu) * rs * gg.z + bb.z;
    v.w = (v.w - mu) * rs * gg.w + bb.w;
    return v;
}
__device__ __forceinline__ void cp_async16(const void* smem_dst, const void* gmem_src) {
    uint32_t sa = (uint32_t)__cvta_generic_to_shared(smem_dst);
    asm volatile("cp.async.cg.shared.global [%0], [%1], 16;"
                 :: "r"(sa), "l"(gmem_src) : "memory");
}
#define CP_COMMIT()  asm volatile("cp.async.commit_group;" ::: "memory")
#define CP_WAIT2()   asm volatile("cp.async.wait_group 2;" ::: "memory")

// ---------------------------------------------------------------------------
// Pipelined TF32 GEMM (4-stage cp.async, cvt at fragment load).
// C[M,N] = A[M,K] @ B[K,N], 256 threads, BM=BN=128, BK=16, warp tile 64x32.
// Bit-identical numerics to the reg-staged version (cvt.rna commutes with
// the fp32 smem round-trip; fragment/MMA order unchanged).
// ---------------------------------------------------------------------------
__global__ __launch_bounds__(256, 2) void gemm_tf32_pipe(
    const float* __restrict__ A, const float* __restrict__ B,
    float* __restrict__ C, int M, int N, int K)
{
    extern __shared__ __align__(16) float smem[];
    float* As = smem;                          // [PSTAGES][128][AS_STRIDE]
    float* Bs = smem + PSTAGES * AS_STAGE;     // [PSTAGES][16][BS_STRIDE]

    const int tid  = threadIdx.x;
    const int warp = tid >> 5, lane = tid & 31;
    const int g    = lane >> 2, q = lane & 3;
    const int wm   = (warp & 1) * 64;
    const int wn   = (warp >> 1) * 32;
    const int m0   = blockIdx.y * 128;
    const int n0   = blockIdx.x * 128;

    const int ar = tid >> 1;            // A row 0..127
    const int ac = (tid & 1) * 8;       // A col 0 or 8
    const int br = tid >> 4;            // B row 0..15
    const int bc = (tid & 15) * 8;      // B col 0..120

    const float* Abase = A + (size_t)(m0 + ar) * K + ac;
    const float* Bbase = B + (size_t)br * N + n0 + bc;

    const int nk = K >> 4;

    // prefill stages 0..2
#pragma unroll
    for (int s = 0; s < PSTAGES - 1; s++) {
        if (s < nk) {
            const float* Ap = Abase + s * 16;
            const float* Bp = Bbase + (size_t)s * 16 * N;
            float* Ad = As + s * AS_STAGE + ar * AS_STRIDE + ac;
            float* Bd = Bs + s * BS_STAGE + br * BS_STRIDE + bc;
            cp_async16(Ad,     Ap);
            cp_async16(Ad + 4, Ap + 4);
            cp_async16(Bd,     Bp);
            cp_async16(Bd + 4, Bp + 4);
        }
        CP_COMMIT();
    }

    float acc[4][4][4];
#pragma unroll
    for (int i = 0; i < 4; i++)
#pragma unroll
        for (int j = 0; j < 4; j++)
#pragma unroll
            for (int k = 0; k < 4; k++) acc[i][j][k] = 0.f;

    for (int kt = 0; kt < nk; kt++) {
        CP_WAIT2();                // stage kt's group complete (per thread)
        __syncthreads();           // all threads' copies visible; prev compute done

        // issue loads for kt+3 into the buffer freed by kt-1
        {
            const int kf = kt + PSTAGES - 1;
            if (kf < nk) {
                const int s = kf & (PSTAGES - 1);
                const float* Ap = Abase + kf * 16;
                const float* Bp = Bbase + (size_t)kf * 16 * N;
                float* Ad = As + s * AS_STAGE + ar * AS_STRIDE + ac;
                float* Bd = Bs + s * BS_STAGE + br * BS_STRIDE + bc;
                cp_async16(Ad,     Ap);
                cp_async16(Ad + 4, Ap + 4);
                cp_async16(Bd,     Bp);
                cp_async16(Bd + 4, Bp + 4);
            }
            CP_COMMIT();
        }

        const float* Ac = As + (kt & (PSTAGES - 1)) * AS_STAGE;
        const float* Bc = Bs + (kt & (PSTAGES - 1)) * BS_STAGE;

#pragma unroll
        for (int ks = 0; ks < 2; ks++) {
            uint32_t af[4][4], bf[4][2];
            const int kk = ks * 8 + q;
#pragma unroll
            for (int tm = 0; tm < 4; tm++) {
                const int r = wm + tm * 16 + g;
                af[tm][0] = tf32_rn(Ac[r * AS_STRIDE + kk]);
                af[tm][1] = tf32_rn(Ac[(r + 8) * AS_STRIDE + kk]);
                af[tm][2] = tf32_rn(Ac[r * AS_STRIDE + kk + 4]);
                af[tm][3] = tf32_rn(Ac[(r + 8) * AS_STRIDE + kk + 4]);
            }
#pragma unroll
            for (int tn = 0; tn < 4; tn++) {
                const int n = wn + tn * 8 + g;
                bf[tn][0] = tf32_rn(Bc[kk * BS_STRIDE + n]);
                bf[tn][1] = tf32_rn(Bc[(kk + 4) * BS_STRIDE + n]);
            }
#pragma unroll
            for (int tm = 0; tm < 4; tm++)
#pragma unroll
                for (int tn = 0; tn < 4; tn++)
                    mma_tf32(acc[tm][tn], af[tm], bf[tn]);
        }
    }

#pragma unroll
    for (int tm = 0; tm < 4; tm++) {
        const int row = m0 + wm + tm * 16 + g;
#pragma unroll
        for (int tn = 0; tn < 4; tn++) {
            const int col = n0 + wn + tn * 8 + 2 * q;
            *(float2*)&C[(size_t)row * N + col] =
                make_float2(acc[tm][tn][0], acc[tm][tn][1]);
            *(float2*)&C[(size_t)(row + 8) * N + col] =
                make_float2(acc[tm][tn][2], acc[tm][tn][3]);
        }
    }
}

// ---------------------------------------------------------------------------
// GEMM2 variant (unchanged R9 reg-staged): applies LayerNorm during staging.
// ---------------------------------------------------------------------------
__global__ __launch_bounds__(256, 2) void gemm_tf32_ln(
    const float* __restrict__ A, const float* __restrict__ B,
    float* __restrict__ C, int M, int N, int K,
    const float* __restrict__ ln_g, const float* __restrict__ ln_b)
{
    __shared__ uint32_t As[2][128][20];
    __shared__ uint32_t Bs[2][16][136];

    const int tid  = threadIdx.x;
    const int warp = tid >> 5, lane = tid & 31;
    const int g    = lane >> 2, q = lane & 3;
    const int wm   = (warp & 1) * 64;
    const int wn   = (warp >> 1) * 32;
    const int m0   = blockIdx.y * 128;
    const int n0   = blockIdx.x * 128;

    const int ar = tid >> 1;
    const int ac = (tid & 1) * 8;
    const int br = tid >> 4;
    const int bc = (tid & 15) * 8;

    const float* Aptr = A + (size_t)(m0 + ar) * K + ac;
    const float* Bptr = B + (size_t)br * N + n0 + bc;

    const float2 st = g_lnstats[m0 + ar];
    const float mu = st.x, rs = st.y;

    float acc[4][4][4];
#pragma unroll
    for (int i = 0; i < 4; i++)
#pragma unroll
        for (int j = 0; j < 4; j++)
#pragma unroll
            for (int k = 0; k < 4; k++) acc[i][j][k] = 0.f;

    {
        float4 a0 = ln_apply(*(const float4*)(Aptr),     mu, rs, ln_g, ln_b, ac);
        float4 a1 = ln_apply(*(const float4*)(Aptr + 4), mu, rs, ln_g, ln_b, ac + 4);
        float4 b0 = *(const float4*)(Bptr);
        float4 b1 = *(const float4*)(Bptr + 4);
        *(uint4*)&As[0][ar][ac]     = cvt4(a0);
        *(uint4*)&As[0][ar][ac + 4] = cvt4(a1);
        *(uint4*)&Bs[0][br][bc]     = cvt4(b0);
        *(uint4*)&Bs[0][br][bc + 4] = cvt4(b1);
    }
    __syncthreads();

    const int nk = K >> 4;
    for (int kt = 0; kt < nk; kt++) {
        const int cur = kt & 1;

        float4 na0, na1, nb0, nb1;
        if (kt + 1 < nk) {
            const float* Ap = Aptr + (kt + 1) * 16;
            const float* Bp = Bptr + (size_t)(kt + 1) * 16 * N;
            const int colb = (kt + 1) * 16 + ac;
            na0 = ln_apply(*(const float4*)(Ap),     mu, rs, ln_g, ln_b, colb);
            na1 = ln_apply(*(const float4*)(Ap + 4), mu, rs, ln_g, ln_b, colb + 4);
            nb0 = *(const float4*)(Bp);
            nb1 = *(const float4*)(Bp + 4);
        }

#pragma unroll
        for (int ks = 0; ks < 2; ks++) {
            uint32_t af[4][4], bf[4][2];
            const int kk = ks * 8 + q;
#pragma unroll
            for (int tm = 0; tm < 4; tm++) {
                const int r = wm + tm * 16 + g;
                af[tm][0] = As[cur][r][kk];
                af[tm][1] = As[cur][r + 8][kk];
                af[tm][2] = As[cur][r][kk + 4];
                af[tm][3] = As[cur][r + 8][kk + 4];
            }
#pragma unroll
            for (int tn = 0; tn < 4; tn++) {
                const int n = wn + tn * 8 + g;
                bf[tn][0] = Bs[cur][kk][n];
                bf[tn][1] = Bs[cur][kk + 4][n];
            }
#pragma unroll
            for (int tm = 0; tm < 4; tm++)
#pragma unroll
                for (int tn = 0; tn < 4; tn++)
                    mma_tf32(acc[tm][tn], af[tm], bf[tn]);
        }

        if (kt + 1 < nk) {
            const int nxt = cur ^ 1;
            *(uint4*)&As[nxt][ar][ac]     = cvt4(na0);
            *(uint4*)&As[nxt][ar][ac + 4] = cvt4(na1);
            *(uint4*)&Bs[nxt][br][bc]     = cvt4(nb0);
            *(uint4*)&Bs[nxt][br][bc + 4] = cvt4(nb1);
        }
        __syncthreads();
    }

#pragma unroll
    for (int tm = 0; tm < 4; tm++) {
        const int row = m0 + wm + tm * 16 + g;
#pragma unroll
        for (int tn = 0; tn < 4; tn++) {
            const int col = n0 + wn + tn * 8 + 2 * q;
            *(float2*)&C[(size_t)row * N + col] =
                make_float2(acc[tm][tn][0], acc[tm][tn][1]);
            *(float2*)&C[(size_t)(row + 8) * N + col] =
                make_float2(acc[tm][tn][2], acc[tm][tn][3]);
        }
    }
}

// ---------------------------------------------------------------------------
// proj + fused depthwise conv + silu.
// ---------------------------------------------------------------------------
__global__ __launch_bounds__(256) void proj_conv_kernel(
    const float* __restrict__ W_xproj, const float* __restrict__ conv_w,
    const float* __restrict__ conv_b)
{
    __shared__ float xr[35][64];
    __shared__ float ws[64][NPROJ];
    __shared__ float xs[32][64];
    const int tid = threadIdx.x;
    const int m0  = blockIdx.x * 32;
    const bool seqstart = ((m0 & (SEQ - 1)) == 0);

    float acc[6];
#pragma unroll
    for (int o = 0; o < 6; o++) acc[o] = 0.f;

    for (int k0 = 0; k0 < DINNER; k0 += 64) {
        for (int t = tid; t < 35 * 64; t += 256) {
            int rr = t >> 6, cc = t & 63;
            float v = 0.f;
            if (!(seqstart && rr < 3))
                v = g_xz[(size_t)(m0 - 3 + rr) * ROWW + k0 + cc];
            xr[rr][cc] = v;
        }
        for (int t = tid; t < 64 * NPROJ; t += 256) {
            int kk = t / NPROJ;
            int j  = t - kk * NPROJ;
            ws[kk][j] = W_xproj[(size_t)(k0 + kk) * NPROJ + j];
        }
        __syncthreads();

        for (int t = tid; t < 32 * 64; t += 256) {
            int r  = t >> 6, cc = t & 63;
            int ch = k0 + cc;
            float4 wv = *(const float4*)(conv_w + (size_t)ch * 4);
            float a = conv_b[ch];
            a = fmaf(wv.x, xr[r][cc],     a);
            a = fmaf(wv.y, xr[r + 1][cc], a);
            a = fmaf(wv.z, xr[r + 2][cc], a);
            a = fmaf(wv.w, xr[r + 3][cc], a);
            xs[r][cc] = silu_acc(a);
        }
        __syncthreads();

#pragma unroll
        for (int o = 0; o < 6; o++) {
            int oi = o * 256 + tid;
            int r  = oi / NPROJ;
            int j  = oi - r * NPROJ;
            float a = acc[o];
#pragma unroll 8
            for (int kk = 0; kk < 64; kk++)
                a = fmaf(xs[r][kk], ws[kk][j], a);
            acc[o] = a;
        }
        __syncthreads();
    }
#pragma unroll
    for (int o = 0; o < 6; o++) {
        int oi = o * 256 + tid;
        int r  = oi / NPROJ;
        int j  = oi - r * NPROJ;
        g_proj[(size_t)(m0 + r) * NPROJ + j] = acc[o];
    }
}

// ---------------------------------------------------------------------------
// Chunked scan, pass 1: rolling-window conv+silu, dt/decay on the fly.
// g_P is the PRODUCT of all 64 per-step decays.
// ---------------------------------------------------------------------------
__global__ __launch_bounds__(128) void scan_pass1(
    const float* __restrict__ W_dt, const float* __restrict__ b_dt,
    const float* __restrict__ A_log, const float* __restrict__ conv_w,
    const float* __restrict__ conv_b)
{
    const int blk = blockIdx.x;
    const int c   = blk & (NCHUNK - 1);
    const int h   = (blk >> 6) & (NHEADS - 1);
    const int b   = blk >> 10;
    const int d   = threadIdx.x;
    const int i   = h * HDIM + d;

    __shared__ float sB[CHUNK][DSTATE];
    __shared__ float sR[CHUNK][NHEADS];
    for (int t = threadIdx.x; t < CHUNK * DSTATE; t += 128) {
        int tt = t >> 4, n = t & 15;
        size_t pm = (size_t)(b * SEQ + c * CHUNK + tt) * NPROJ;
        sB[tt][n] = g_proj[pm + NHEADS + n];
        sR[tt][n] = g_proj[pm + n];
    }
    __syncthreads();

    float w[NHEADS];
#pragma unroll
    for (int hh = 0; hh < NHEADS; hh++) w[hh] = W_dt[(size_t)hh * DINNER + i];
    const float bd = b_dt[i];
    const float Ah = -expf(A_log[h]);
    const float4 cw = *(const float4*)(conv_w + (size_t)i * 4);
    const float cb = conv_b[i];

    const int mbase = b * SEQ + c * CHUNK;
    float x3 = 0.f, x2 = 0.f, x1 = 0.f;
    if (c > 0) {
        x3 = g_xz[(size_t)(mbase - 3) * ROWW + i];
        x2 = g_xz[(size_t)(mbase - 2) * ROWW + i];
        x1 = g_xz[(size_t)(mbase - 1) * ROWW + i];
    }

    float s[DSTATE];
#pragma unroll
    for (int n = 0; n < DSTATE; n++) s[n] = 0.f;
    float cum = 0.f;
    float P   = 1.f;

    for (int tt = 0; tt < CHUNK; tt++) {
        float raw = bd;
#pragma unroll
        for (int hh = 0; hh < NHEADS; hh++) raw = fmaf(sR[tt][hh], w[hh], raw);
        float dtv = softplus_acc(raw);
        cum += dtv;
        float a = expf(Ah * cum);
        P *= a;

        float x0 = g_xz[(size_t)(mbase + tt) * ROWW + i];
        float cv = cb;
        cv = fmaf(cw.x, x3, cv);
        cv = fmaf(cw.y, x2, cv);
        cv = fmaf(cw.z, x1, cv);
        cv = fmaf(cw.w, x0, cv);
        float xc = silu_acc(cv);
        x3 = x2; x2 = x1; x1 = x0;

        float u = dtv * xc;
#pragma unroll
        for (int n = 0; n < DSTATE; n++)
            s[n] = fmaf(s[n], a, u * sB[tt][n]);
    }
    const int base = ((b * NHEADS + h) * NCHUNK + c) * HDIM + d;
    g_P[base] = P;
#pragma unroll
    for (int n = 0; n < DSTATE; n++) g_S[(size_t)base * DSTATE + n] = s[n];
}

// ---------------------------------------------------------------------------
// Pass 2: stitch across chunks (separate in/out buffers -> pipelined loads).
// ---------------------------------------------------------------------------
__global__ __launch_bounds__(256) void scan_pass2()
{
    const int idx = blockIdx.x * 256 + threadIdx.x;   // BATCH*NHEADS*HDIM*DSTATE
    const int n   = idx & (DSTATE - 1);
    const int d   = (idx >> 4) & (HDIM - 1);
    const int bh  = idx >> 11;                        // 0..31

    float s = 0.f;
#pragma unroll 8
    for (int c = 0; c < NCHUNK; c++) {
        const int base = (bh * NCHUNK + c) * HDIM + d;
        const float Pv = g_P[base];
        const size_t off = (size_t)base * DSTATE + n;
        const float Sl = g_S[off];
        g_Sin[off] = s;               // incoming state for chunk c
        s = fmaf(Pv, s, Sl);
    }
}

// ---------------------------------------------------------------------------
// Pass 3: replay (rolling conv) + y = C.s + D*x, gate with silu(z) -> g_y raw
// ---------------------------------------------------------------------------
__global__ __launch_bounds__(128) void scan_pass3(
    const float* __restrict__ W_dt, const float* __restrict__ b_dt,
    const float* __restrict__ A_log, const float* __restrict__ D_skip,
    const float* __restrict__ conv_w, const float* __restrict__ conv_b)
{
    const int blk = blockIdx.x;
    const int c   = blk & (NCHUNK - 1);
    const int h   = (blk >> 6) & (NHEADS - 1);
    const int b   = blk >> 10;
    const int d   = threadIdx.x;
    const int i   = h * HDIM + d;

    __shared__ float sB[CHUNK][DSTATE];
    __shared__ float sC[CHUNK][DSTATE];
    __shared__ float sR[CHUNK][NHEADS];
    for (int t = threadIdx.x; t < CHUNK * DSTATE; t += 128) {
        int tt = t >> 4, n = t & 15;
        size_t pm = (size_t)(b * SEQ + c * CHUNK + tt) * NPROJ;
        sB[tt][n] = g_proj[pm + NHEADS + n];
        sC[tt][n] = g_proj[pm + NHEADS + DSTATE + n];
        sR[tt][n] = g_proj[pm + n];
    }
    __syncthreads();

    float w[NHEADS];
#pragma unroll
    for (int hh = 0; hh < NHEADS; hh++) w[hh] = W_dt[(size_t)hh * DINNER + i];
    const float bd = b_dt[i];
    const float Ah = -expf(A_log[h]);
    const float Dh = D_skip[h];
    const float4 cw = *(const float4*)(conv_w + (size_t)i * 4);
    const float cb = conv_b[i];

    const int base = ((b * NHEADS + h) * NCHUNK + c) * HDIM + d;
    float s[DSTATE];
#pragma unroll
    for (int n = 0; n < DSTATE; n++) s[n] = g_Sin[(size_t)base * DSTATE + n];

    const int mbase = b * SEQ + c * CHUNK;
    float x3 = 0.f, x2 = 0.f, x1 = 0.f;
    if (c > 0) {
        x3 = g_xz[(size_t)(mbase - 3) * ROWW + i];
        x2 = g_xz[(size_t)(mbase - 2) * ROWW + i];
        x1 = g_xz[(size_t)(mbase - 1) * ROWW + i];
    }

    float cum = 0.f;
    for (int tt = 0; tt < CHUNK; tt++) {
        float raw = bd;
#pragma unroll
        for (int hh = 0; hh < NHEADS; hh++) raw = fmaf(sR[tt][hh], w[hh], raw);
        float dtv = softplus_acc(raw);
        cum += dtv;
        float a = expf(Ah * cum);

        const size_t rowoff = (size_t)(mbase + tt) * ROWW;
        float x0 = g_xz[rowoff + i];
        float cv = cb;
        cv = fmaf(cw.x, x3, cv);
        cv = fmaf(cw.y, x2, cv);
        cv = fmaf(cw.z, x1, cv);
        cv = fmaf(cw.w, x0, cv);
        float xc = silu_acc(cv);
        x3 = x2; x2 = x1; x1 = x0;

        float u = dtv * xc;
        float y = 0.f;
#pragma unroll
        for (int n = 0; n < DSTATE; n++) {
            s[n] = fmaf(s[n], a, u * sB[tt][n]);
            y    = fmaf(s[n], sC[tt][n], y);
        }
        y = fmaf(Dh, xc, y);
        float zv = g_xz[rowoff + DINNER + i];
        y *= silu_acc(zv);
        g_y[(size_t)(mbase + tt) * DINNER + i] = y;
    }
}

// ---------------------------------------------------------------------------
// LayerNorm stats only: per-row {mu, rstd} -> g_lnstats.
// ---------------------------------------------------------------------------
__global__ __launch_bounds__(256) void ln_stats_kernel()
{
    __shared__ float sh[8];
    __shared__ float s_mu;
    const int m   = blockIdx.x;
    const int tid = threadIdx.x;
    const float* row = g_y + (size_t)m * DINNER;

    const int i0 = tid * 4;
    float4 a  = *(const float4*)(row + i0);
    float4 b4 = *(const float4*)(row + 1024 + i0);
    float v[8] = {a.x, a.y, a.z, a.w, b4.x, b4.y, b4.z, b4.w};

    float sum = 0.f;
#pragma unroll
    for (int k = 0; k < 8; k++) sum += v[k];
#pragma unroll
    for (int o = 16; o > 0; o >>= 1) sum += __shfl_xor_sync(0xffffffffu, sum, o);
    if ((tid & 31) == 0) sh[tid >> 5] = sum;
    __syncthreads();
    if (tid < 32) {
        float t = (tid < 8) ? sh[tid] : 0.f;
#pragma unroll
        for (int o = 4; o > 0; o >>= 1) t += __shfl_xor_sync(0xffffffffu, t, o);
        if (tid == 0) s_mu = t * (1.f / (float)DINNER);
    }
    __syncthreads();
    const float mu = s_mu;

    float var = 0.f;
#pragma unroll
    for (int k = 0; k < 8; k++) { float dv = v[k] - mu; var = fmaf(dv, dv, var); }
#pragma unroll
    for (int o = 16; o > 0; o >>= 1) var += __shfl_xor_sync(0xffffffffu, var, o);
    __syncthreads();
    if ((tid & 31) == 0) sh[tid >> 5] = var;
    __syncthreads();
    if (tid < 32) {
        float t = (tid < 8) ? sh[tid] : 0.f;
#pragma unroll
        for (int o = 4; o > 0; o >>= 1) t += __shfl_xor_sync(0xffffffffu, t, o);
        if (tid == 0) {
            float rstd = rsqrtf(t * (1.f / (float)DINNER) + LN_EPS);
            g_lnstats[m] = make_float2(mu, rstd);
        }
    }
}

// ---------------------------------------------------------------------------
// kernel_launch
// ---------------------------------------------------------------------------
extern "C" void kernel_launch(void* const* d_in, const int* in_sizes, int n_in,
                              void* d_out, int out_size)
{
    const float* x       = (const float*)d_in[0];
    const float* W_in    = (const float*)d_in[1];
    const float* conv_w  = (const float*)d_in[2];
    const float* conv_b  = (const float*)d_in[3];
    const float* W_xproj = (const float*)d_in[4];
    const float* W_dt    = (const float*)d_in[5];
    const float* b_dt    = (const float*)d_in[6];
    const float* A_log   = (const float*)d_in[7];
    const float* D_skip  = (const float*)d_in[8];
    const float* W_out   = (const float*)d_in[9];
    const float* ln_g    = (const float*)d_in[10];
    const float* ln_b    = (const float*)d_in[11];
    float* out = (float*)d_out;

    float *pxz = nullptr, *py = nullptr;
    cudaGetSymbolAddress((void**)&pxz, g_xz);
    cudaGetSymbolAddress((void**)&py,  g_y);

    // Opt-in to >48KB dynamic smem for the pipelined GEMM (idempotent).
    cudaFuncSetAttribute(gemm_tf32_pipe,
                         cudaFuncAttributeMaxDynamicSharedMemorySize,
                         PIPE_SMEM_BYTES);

    // 1) xz = x @ W_in   [8192,1024]x[1024,4096]  (4-stage cp.async pipeline)
    dim3 g1(2 * DINNER / 128, M_ROWS / 128);
    gemm_tf32_pipe<<<g1, 256, PIPE_SMEM_BYTES>>>(x, W_in, pxz,
                                                 M_ROWS, 2 * DINNER, DMODEL);

    // 2) proj = silu(conv(xe)) @ W_xproj
    proj_conv_kernel<<<M_ROWS / 32, 256>>>(W_xproj, conv_w, conv_b);

    // 3) chunked scan
    scan_pass1<<<BATCH * NHEADS * NCHUNK, 128>>>(W_dt, b_dt, A_log, conv_w, conv_b);
    scan_pass2<<<(BATCH * NHEADS * HDIM * DSTATE) / 256, 256>>>();
    scan_pass3<<<BATCH * NHEADS * NCHUNK, 128>>>(W_dt, b_dt, A_log, D_skip, conv_w, conv_b);

    // 4) LN stats; normalization fused into GEMM2 staging
    ln_stats_kernel<<<M_ROWS, 256>>>();

    // 5) out = LN(y) @ W_out   [8192,2048]x[2048,1024]  (unchanged reg-staged)
    dim3 g2(DMODEL / 128, M_ROWS / 128);
    gemm_tf32_ln<<<g2, 256>>>(py, W_out, out, M_ROWS, DMODEL, DINNER, ln_g, ln_b);
}

// round 11
// speedup vs baseline: 1.1627x; 1.0792x over previous
#include <cuda_runtime.h>
#include <math.h>
#include <stdint.h>

// ---------------------------------------------------------------------------
// Problem constants
// ---------------------------------------------------------------------------
#define BATCH   2
#define SEQ     4096
#define DMODEL  1024
#define DINNER  2048
#define NHEADS  16
#define HDIM    128
#define DSTATE  16
#define DCONV   4
#define CHUNK   64
#define NCHUNK  (SEQ / CHUNK)      // 64
#define M_ROWS  (BATCH * SEQ)      // 8192
#define NPROJ   (NHEADS + 2*DSTATE) // 48
#define ROWW    (2 * DINNER)        // g_xz row width
#define LN_EPS  1e-5f

// Pipelined GEMM config
#define PSTAGES    4
#define AS_STRIDE  20                 // padded row pitch (floats)
#define BS_STRIDE  136                // padded row pitch (floats)
#define AS_STAGE   (128 * AS_STRIDE)  // 2560 floats
#define BS_STAGE   (16 * BS_STRIDE)   // 2176 floats
#define PIPE_SMEM_BYTES ((PSTAGES * (AS_STAGE + BS_STAGE)) * 4)  // 75776 B

// ---------------------------------------------------------------------------
// Scratch (static device globals -- no allocation allowed)
// ---------------------------------------------------------------------------
__device__ float  g_xz[(size_t)M_ROWS * ROWW];          // [xe | z]
__device__ float  g_proj[(size_t)M_ROWS * NPROJ];       // dt_raw | B | C
__device__ float  g_y[(size_t)M_ROWS * DINNER];         // raw gated y (pre-LN)
__device__ float  g_yn[(size_t)M_ROWS * DINNER];        // tf32-rounded LN(y)
__device__ float  g_S[(size_t)BATCH*NHEADS*NCHUNK*HDIM*DSTATE];   // chunk-local states
__device__ float  g_Sin[(size_t)BATCH*NHEADS*NCHUNK*HDIM*DSTATE]; // incoming states
__device__ float  g_P[(size_t)BATCH*NHEADS*NCHUNK*HDIM];
__device__ float  g_xr [(size_t)M_ROWS * DMODEL];       // tf32-rounded x
__device__ float  g_w1r[(size_t)DMODEL * 2 * DINNER];   // tf32-rounded W_in
__device__ float  g_w2r[(size_t)DINNER * DMODEL];       // tf32-rounded W_out

// ---------------------------------------------------------------------------
// Helpers
// ---------------------------------------------------------------------------
__device__ __forceinline__ uint32_t tf32_rn(float x) {
    uint32_t r;
    asm("cvt.rna.tf32.f32 %0, %1;" : "=r"(r) : "f"(x));
    return r;
}
__device__ __forceinline__ float4 round4(float4 v) {
    v.x = __uint_as_float(tf32_rn(v.x));
    v.y = __uint_as_float(tf32_rn(v.y));
    v.z = __uint_as_float(tf32_rn(v.z));
    v.w = __uint_as_float(tf32_rn(v.w));
    return v;
}
__device__ __forceinline__ void mma_tf32(float* c, const uint32_t* a, const uint32_t* b) {
    asm volatile(
        "mma.sync.aligned.m16n8k8.row.col.f32.tf32.tf32.f32 "
        "{%0,%1,%2,%3},{%4,%5,%6,%7},{%8,%9},{%0,%1,%2,%3};"
        : "+f"(c[0]), "+f"(c[1]), "+f"(c[2]), "+f"(c[3])
        : "r"(a[0]), "r"(a[1]), "r"(a[2]), "r"(a[3]), "r"(b[0]), "r"(b[1]));
}
__device__ __forceinline__ float softplus_acc(float x) {
    return (x > 20.f) ? x : log1pf(expf(x));
}
__device__ __forceinline__ float silu_acc(float v) {
    return v / (1.f + expf(-v));
}
__device__ __forceinline__ float4 ln_apply(float4 v, float mu, float rs,
                                           const float* __restrict__ g,
                                           const float* __restrict__ b, int col) {
    float4 gg = *(const float4*)(g + col);
    float4 bb = *(const float4*)(b + col);
    v.x = (v.x - mu) * rs * gg.x + bb.x;
    v.y = (v.y - mu) * rs * gg.y + bb.y;
    v.z = (v.z - mu) * rs * gg.z + bb.z;
    v.w = (v.w - mu) * rs * gg.w + bb.w;
    return v;
}
__device__ __forceinline__ void cp_async16(const void* smem_dst, const void* gmem_src) {
    uint32_t sa = (uint32_t)__cvta_generic_to_shared(smem_dst);
    asm volatile("cp.async.cg.shared.global [%0], [%1], 16;"
                 :: "r"(sa), "l"(gmem_src) : "memory");
}
#define CP_COMMIT()  asm volatile("cp.async.commit_group;" ::: "memory")
#define CP_WAIT2()   asm volatile("cp.async.wait_group 2;" ::: "memory")

// ---------------------------------------------------------------------------
// Elementwise tf32 pre-round: dst = round_tf32(src). n multiple of 4.
// ---------------------------------------------------------------------------
__global__ __launch_bounds__(256) void round_tf32_kernel(
    const float* __restrict__ src, float* __restrict__ dst, int n4)
{
    int i = blockIdx.x * 256 + threadIdx.x;
    if (i < n4)
        *(float4*)(dst + 4 * (size_t)i) = round4(*(const float4*)(src + 4 * (size_t)i));
}

// ---------------------------------------------------------------------------
// Pipelined TF32 GEMM, cvt-free (operands pre-rounded to tf32 bit patterns).
// C[M,N] = A[M,K] @ B[K,N], 256 threads, BM=BN=128, BK=16, warp tile 64x32.
// ---------------------------------------------------------------------------
__global__ __launch_bounds__(256, 2) void gemm_tf32_pipe(
    const float* __restrict__ A, const float* __restrict__ B,
    float* __restrict__ C, int M, int N, int K)
{
    extern __shared__ __align__(16) float smem[];
    float* As = smem;                          // [PSTAGES][128][AS_STRIDE]
    float* Bs = smem + PSTAGES * AS_STAGE;     // [PSTAGES][16][BS_STRIDE]

    const int tid  = threadIdx.x;
    const int warp = tid >> 5, lane = tid & 31;
    const int g    = lane >> 2, q = lane & 3;
    const int wm   = (warp & 1) * 64;
    const int wn   = (warp >> 1) * 32;
    const int m0   = blockIdx.y * 128;
    const int n0   = blockIdx.x * 128;

    const int ar = tid >> 1;            // A row 0..127
    const int ac = (tid & 1) * 8;       // A col 0 or 8
    const int br = tid >> 4;            // B row 0..15
    const int bc = (tid & 15) * 8;      // B col 0..120

    const float* Abase = A + (size_t)(m0 + ar) * K + ac;
    const float* Bbase = B + (size_t)br * N + n0 + bc;

    const int nk = K >> 4;

    // prefill stages 0..2
#pragma unroll
    for (int s = 0; s < PSTAGES - 1; s++) {
        if (s < nk) {
            const float* Ap = Abase + s * 16;
            const float* Bp = Bbase + (size_t)s * 16 * N;
            float* Ad = As + s * AS_STAGE + ar * AS_STRIDE + ac;
            float* Bd = Bs + s * BS_STAGE + br * BS_STRIDE + bc;
            cp_async16(Ad,     Ap);
            cp_async16(Ad + 4, Ap + 4);
            cp_async16(Bd,     Bp);
            cp_async16(Bd + 4, Bp + 4);
        }
        CP_COMMIT();
    }

    float acc[4][4][4];
#pragma unroll
    for (int i = 0; i < 4; i++)
#pragma unroll
        for (int j = 0; j < 4; j++)
#pragma unroll
            for (int k = 0; k < 4; k++) acc[i][j][k] = 0.f;

    for (int kt = 0; kt < nk; kt++) {
        CP_WAIT2();
        __syncthreads();

        {
            const int kf = kt + PSTAGES - 1;
            if (kf < nk) {
                const int s = kf & (PSTAGES - 1);
                const float* Ap = Abase + kf * 16;
                const float* Bp = Bbase + (size_t)kf * 16 * N;
                float* Ad = As + s * AS_STAGE + ar * AS_STRIDE + ac;
                float* Bd = Bs + s * BS_STAGE + br * BS_STRIDE + bc;
                cp_async16(Ad,     Ap);
                cp_async16(Ad + 4, Ap + 4);
                cp_async16(Bd,     Bp);
                cp_async16(Bd + 4, Bp + 4);
            }
            CP_COMMIT();
        }

        const float* Ac = As + (kt & (PSTAGES - 1)) * AS_STAGE;
        const float* Bc = Bs + (kt & (PSTAGES - 1)) * BS_STAGE;

#pragma unroll
        for (int ks = 0; ks < 2; ks++) {
            uint32_t af[4][4], bf[4][2];
            const int kk = ks * 8 + q;
#pragma unroll
            for (int tm = 0; tm < 4; tm++) {
                const int r = wm + tm * 16 + g;
                af[tm][0] = __float_as_uint(Ac[r * AS_STRIDE + kk]);
                af[tm][1] = __float_as_uint(Ac[(r + 8) * AS_STRIDE + kk]);
                af[tm][2] = __float_as_uint(Ac[r * AS_STRIDE + kk + 4]);
                af[tm][3] = __float_as_uint(Ac[(r + 8) * AS_STRIDE + kk + 4]);
            }
#pragma unroll
            for (int tn = 0; tn < 4; tn++) {
                const int n = wn + tn * 8 + g;
                bf[tn][0] = __float_as_uint(Bc[kk * BS_STRIDE + n]);
                bf[tn][1] = __float_as_uint(Bc[(kk + 4) * BS_STRIDE + n]);
            }
#pragma unroll
            for (int tm = 0; tm < 4; tm++)
#pragma unroll
                for (int tn = 0; tn < 4; tn++)
                    mma_tf32(acc[tm][tn], af[tm], bf[tn]);
        }
    }

#pragma unroll
    for (int tm = 0; tm < 4; tm++) {
        const int row = m0 + wm + tm * 16 + g;
#pragma unroll
        for (int tn = 0; tn < 4; tn++) {
            const int col = n0 + wn + tn * 8 + 2 * q;
            *(float2*)&C[(size_t)row * N + col] =
                make_float2(acc[tm][tn][0], acc[tm][tn][1]);
            *(float2*)&C[(size_t)(row + 8) * N + col] =
                make_float2(acc[tm][tn][2], acc[tm][tn][3]);
        }
    }
}

// ---------------------------------------------------------------------------
// proj + fused depthwise conv + silu.
// ---------------------------------------------------------------------------
__global__ __launch_bounds__(256) void proj_conv_kernel(
    const float* __restrict__ W_xproj, const float* __restrict__ conv_w,
    const float* __restrict__ conv_b)
{
    __shared__ float xr[35][64];
    __shared__ float ws[64][NPROJ];
    __shared__ float xs[32][64];
    const int tid = threadIdx.x;
    const int m0  = blockIdx.x * 32;
    const bool seqstart = ((m0 & (SEQ - 1)) == 0);

    float acc[6];
#pragma unroll
    for (int o = 0; o < 6; o++) acc[o] = 0.f;

    for (int k0 = 0; k0 < DINNER; k0 += 64) {
        for (int t = tid; t < 35 * 64; t += 256) {
            int rr = t >> 6, cc = t & 63;
            float v = 0.f;
            if (!(seqstart && rr < 3))
                v = g_xz[(size_t)(m0 - 3 + rr) * ROWW + k0 + cc];
            xr[rr][cc] = v;
        }
        for (int t = tid; t < 64 * NPROJ; t += 256) {
            int kk = t / NPROJ;
            int j  = t - kk * NPROJ;
            ws[kk][j] = W_xproj[(size_t)(k0 + kk) * NPROJ + j];
        }
        __syncthreads();

        for (int t = tid; t < 32 * 64; t += 256) {
            int r  = t >> 6, cc = t & 63;
            int ch = k0 + cc;
            float4 wv = *(const float4*)(conv_w + (size_t)ch * 4);
            float a = conv_b[ch];
            a = fmaf(wv.x, xr[r][cc],     a);
            a = fmaf(wv.y, xr[r + 1][cc], a);
            a = fmaf(wv.z, xr[r + 2][cc], a);
            a = fmaf(wv.w, xr[r + 3][cc], a);
            xs[r][cc] = silu_acc(a);
        }
        __syncthreads();

#pragma unroll
        for (int o = 0; o < 6; o++) {
            int oi = o * 256 + tid;
            int r  = oi / NPROJ;
            int j  = oi - r * NPROJ;
            float a = acc[o];
#pragma unroll 8
            for (int kk = 0; kk < 64; kk++)
                a = fmaf(xs[r][kk], ws[kk][j], a);
            acc[o] = a;
        }
        __syncthreads();
    }
#pragma unroll
    for (int o = 0; o < 6; o++) {
        int oi = o * 256 + tid;
        int r  = oi / NPROJ;
        int j  = oi - r * NPROJ;
        g_proj[(size_t)(m0 + r) * NPROJ + j] = acc[o];
    }
}

// ---------------------------------------------------------------------------
// Chunked scan, pass 1: rolling-window conv+silu, dt/decay on the fly.
// g_P is the PRODUCT of all 64 per-step decays.
// ---------------------------------------------------------------------------
__global__ __launch_bounds__(128) void scan_pass1(
    const float* __restrict__ W_dt, const float* __restrict__ b_dt,
    const float* __restrict__ A_log, const float* __restrict__ conv_w,
    const float* __restrict__ conv_b)
{
    const int blk = blockIdx.x;
    const int c   = blk & (NCHUNK - 1);
    const int h   = (blk >> 6) & (NHEADS - 1);
    const int b   = blk >> 10;
    const int d   = threadIdx.x;
    const int i   = h * HDIM + d;

    __shared__ float sB[CHUNK][DSTATE];
    __shared__ float sR[CHUNK][NHEADS];
    for (int t = threadIdx.x; t < CHUNK * DSTATE; t += 128) {
        int tt = t >> 4, n = t & 15;
        size_t pm = (size_t)(b * SEQ + c * CHUNK + tt) * NPROJ;
        sB[tt][n] = g_proj[pm + NHEADS + n];
        sR[tt][n] = g_proj[pm + n];
    }
    __syncthreads();

    float w[NHEADS];
#pragma unroll
    for (int hh = 0; hh < NHEADS; hh++) w[hh] = W_dt[(size_t)hh * DINNER + i];
    const float bd = b_dt[i];
    const float Ah = -expf(A_log[h]);
    const float4 cw = *(const float4*)(conv_w + (size_t)i * 4);
    const float cb = conv_b[i];

    const int mbase = b * SEQ + c * CHUNK;
    float x3 = 0.f, x2 = 0.f, x1 = 0.f;
    if (c > 0) {
        x3 = g_xz[(size_t)(mbase - 3) * ROWW + i];
        x2 = g_xz[(size_t)(mbase - 2) * ROWW + i];
        x1 = g_xz[(size_t)(mbase - 1) * ROWW + i];
    }

    float s[DSTATE];
#pragma unroll
    for (int n = 0; n < DSTATE; n++) s[n] = 0.f;
    float cum = 0.f;
    float P   = 1.f;

    for (int tt = 0; tt < CHUNK; tt++) {
        float raw = bd;
#pragma unroll
        for (int hh = 0; hh < NHEADS; hh++) raw = fmaf(sR[tt][hh], w[hh], raw);
        float dtv = softplus_acc(raw);
        cum += dtv;
        float a = expf(Ah * cum);
        P *= a;

        float x0 = g_xz[(size_t)(mbase + tt) * ROWW + i];
        float cv = cb;
        cv = fmaf(cw.x, x3, cv);
        cv = fmaf(cw.y, x2, cv);
        cv = fmaf(cw.z, x1, cv);
        cv = fmaf(cw.w, x0, cv);
        float xc = silu_acc(cv);
        x3 = x2; x2 = x1; x1 = x0;

        float u = dtv * xc;
#pragma unroll
        for (int n = 0; n < DSTATE; n++)
            s[n] = fmaf(s[n], a, u * sB[tt][n]);
    }
    const int base = ((b * NHEADS + h) * NCHUNK + c) * HDIM + d;
    g_P[base] = P;
#pragma unroll
    for (int n = 0; n < DSTATE; n++) g_S[(size_t)base * DSTATE + n] = s[n];
}

// ---------------------------------------------------------------------------
// Pass 2: stitch across chunks (separate in/out buffers -> pipelined loads).
// ---------------------------------------------------------------------------
__global__ __launch_bounds__(256) void scan_pass2()
{
    const int idx = blockIdx.x * 256 + threadIdx.x;   // BATCH*NHEADS*HDIM*DSTATE
    const int n   = idx & (DSTATE - 1);
    const int d   = (idx >> 4) & (HDIM - 1);
    const int bh  = idx >> 11;                        // 0..31

    float s = 0.f;
#pragma unroll 8
    for (int c = 0; c < NCHUNK; c++) {
        const int base = (bh * NCHUNK + c) * HDIM + d;
        const float Pv = g_P[base];
        const size_t off = (size_t)base * DSTATE + n;
        const float Sl = g_S[off];
        g_Sin[off] = s;               // incoming state for chunk c
        s = fmaf(Pv, s, Sl);
    }
}

// ---------------------------------------------------------------------------
// Pass 3: replay (rolling conv) + y = C.s + D*x, gate with silu(z) -> g_y raw
// ---------------------------------------------------------------------------
__global__ __launch_bounds__(128) void scan_pass3(
    const float* __restrict__ W_dt, const float* __restrict__ b_dt,
    const float* __restrict__ A_log, const float* __restrict__ D_skip,
    const float* __restrict__ conv_w, const float* __restrict__ conv_b)
{
    const int blk = blockIdx.x;
    const int c   = blk & (NCHUNK - 1);
    const int h   = (blk >> 6) & (NHEADS - 1);
    const int b   = blk >> 10;
    const int d   = threadIdx.x;
    const int i   = h * HDIM + d;

    __shared__ float sB[CHUNK][DSTATE];
    __shared__ float sC[CHUNK][DSTATE];
    __shared__ float sR[CHUNK][NHEADS];
    for (int t = threadIdx.x; t < CHUNK * DSTATE; t += 128) {
        int tt = t >> 4, n = t & 15;
        size_t pm = (size_t)(b * SEQ + c * CHUNK + tt) * NPROJ;
        sB[tt][n] = g_proj[pm + NHEADS + n];
        sC[tt][n] = g_proj[pm + NHEADS + DSTATE + n];
        sR[tt][n] = g_proj[pm + n];
    }
    __syncthreads();

    float w[NHEADS];
#pragma unroll
    for (int hh = 0; hh < NHEADS; hh++) w[hh] = W_dt[(size_t)hh * DINNER + i];
    const float bd = b_dt[i];
    const float Ah = -expf(A_log[h]);
    const float Dh = D_skip[h];
    const float4 cw = *(const float4*)(conv_w + (size_t)i * 4);
    const float cb = conv_b[i];

    const int base = ((b * NHEADS + h) * NCHUNK + c) * HDIM + d;
    float s[DSTATE];
#pragma unroll
    for (int n = 0; n < DSTATE; n++) s[n] = g_Sin[(size_t)base * DSTATE + n];

    const int mbase = b * SEQ + c * CHUNK;
    float x3 = 0.f, x2 = 0.f, x1 = 0.f;
    if (c > 0) {
        x3 = g_xz[(size_t)(mbase - 3) * ROWW + i];
        x2 = g_xz[(size_t)(mbase - 2) * ROWW + i];
        x1 = g_xz[(size_t)(mbase - 1) * ROWW + i];
    }

    float cum = 0.f;
    for (int tt = 0; tt < CHUNK; tt++) {
        float raw = bd;
#pragma unroll
        for (int hh = 0; hh < NHEADS; hh++) raw = fmaf(sR[tt][hh], w[hh], raw);
        float dtv = softplus_acc(raw);
        cum += dtv;
        float a = expf(Ah * cum);

        const size_t rowoff = (size_t)(mbase + tt) * ROWW;
        float x0 = g_xz[rowoff + i];
        float cv = cb;
        cv = fmaf(cw.x, x3, cv);
        cv = fmaf(cw.y, x2, cv);
        cv = fmaf(cw.z, x1, cv);
        cv = fmaf(cw.w, x0, cv);
        float xc = silu_acc(cv);
        x3 = x2; x2 = x1; x1 = x0;

        float u = dtv * xc;
        float y = 0.f;
#pragma unroll
        for (int n = 0; n < DSTATE; n++) {
            s[n] = fmaf(s[n], a, u * sB[tt][n]);
            y    = fmaf(s[n], sC[tt][n], y);
        }
        y = fmaf(Dh, xc, y);
        float zv = g_xz[rowoff + DINNER + i];
        y *= silu_acc(zv);
        g_y[(size_t)(mbase + tt) * DINNER + i] = y;
    }
}

// ---------------------------------------------------------------------------
// LayerNorm stats + apply + tf32 round: g_y -> g_yn (ready for cvt-free GEMM2).
// ---------------------------------------------------------------------------
__global__ __launch_bounds__(256) void ln_apply_kernel(
    const float* __restrict__ ln_g, const float* __restrict__ ln_b)
{
    __shared__ float sh[8];
    __shared__ float s_mu, s_rstd;
    const int m   = blockIdx.x;
    const int tid = threadIdx.x;
    const float* row = g_y + (size_t)m * DINNER;
    float* rown = g_yn + (size_t)m * DINNER;

    const int i0 = tid * 4;
    float4 a  = *(const float4*)(row + i0);
    float4 b4 = *(const float4*)(row + 1024 + i0);
    float v[8] = {a.x, a.y, a.z, a.w, b4.x, b4.y, b4.z, b4.w};

    float sum = 0.f;
#pragma unroll
    for (int k = 0; k < 8; k++) sum += v[k];
#pragma unroll
    for (int o = 16; o > 0; o >>= 1) sum += __shfl_xor_sync(0xffffffffu, sum, o);
    if ((tid & 31) == 0) sh[tid >> 5] = sum;
    __syncthreads();
    if (tid < 32) {
        float t = (tid < 8) ? sh[tid] : 0.f;
#pragma unroll
        for (int o = 4; o > 0; o >>= 1) t += __shfl_xor_sync(0xffffffffu, t, o);
        if (tid == 0) s_mu = t * (1.f / (float)DINNER);
    }
    __syncthreads();
    const float mu = s_mu;

    float var = 0.f;
#pragma unroll
    for (int k = 0; k < 8; k++) { float dv = v[k] - mu; var = fmaf(dv, dv, var); }
#pragma unroll
    for (int o = 16; o > 0; o >>= 1) var += __shfl_xor_sync(0xffffffffu, var, o);
    __syncthreads();
    if ((tid & 31) == 0) sh[tid >> 5] = var;
    __syncthreads();
    if (tid < 32) {
        float t = (tid < 8) ? sh[tid] : 0.f;
#pragma unroll
        for (int o = 4; o > 0; o >>= 1) t += __shfl_xor_sync(0xffffffffu, t, o);
        if (tid == 0) s_rstd = rsqrtf(t * (1.f / (float)DINNER) + LN_EPS);
    }
    __syncthreads();
    const float rs = s_rstd;

    float4 lo = make_float4(v[0], v[1], v[2], v[3]);
    float4 hi = make_float4(v[4], v[5], v[6], v[7]);
    *(float4*)(rown + i0)        = round4(ln_apply(lo, mu, rs, ln_g, ln_b, i0));
    *(float4*)(rown + 1024 + i0) = round4(ln_apply(hi, mu, rs, ln_g, ln_b, 1024 + i0));
}

// ---------------------------------------------------------------------------
// kernel_launch
// ---------------------------------------------------------------------------
extern "C" void kernel_launch(void* const* d_in, const int* in_sizes, int n_in,
                              void* d_out, int out_size)
{
    const float* x       = (const float*)d_in[0];
    const float* W_in    = (const float*)d_in[1];
    const float* conv_w  = (const float*)d_in[2];
    const float* conv_b  = (const float*)d_in[3];
    const float* W_xproj = (const float*)d_in[4];
    const float* W_dt    = (const float*)d_in[5];
    const float* b_dt    = (const float*)d_in[6];
    const float* A_log   = (const float*)d_in[7];
    const float* D_skip  = (const float*)d_in[8];
    const float* W_out   = (const float*)d_in[9];
    const float* ln_g    = (const float*)d_in[10];
    const float* ln_b    = (const float*)d_in[11];
    float* out = (float*)d_out;

    float *pxz = nullptr, *pxr = nullptr, *pw1 = nullptr, *pw2 = nullptr, *pyn = nullptr;
    cudaGetSymbolAddress((void**)&pxz, g_xz);
    cudaGetSymbolAddress((void**)&pxr, g_xr);
    cudaGetSymbolAddress((void**)&pw1, g_w1r);
    cudaGetSymbolAddress((void**)&pw2, g_w2r);
    cudaGetSymbolAddress((void**)&pyn, g_yn);

    cudaFuncSetAttribute(gemm_tf32_pipe,
                         cudaFuncAttributeMaxDynamicSharedMemorySize,
                         PIPE_SMEM_BYTES);

    // 0) tf32 pre-round of GEMM operands (idempotent with MMA-input cvt)
    {
        int nx = (M_ROWS * DMODEL) / 4;
        round_tf32_kernel<<<(nx + 255) / 256, 256>>>(x, pxr, nx);
        int nw1 = (DMODEL * 2 * DINNER) / 4;
        round_tf32_kernel<<<(nw1 + 255) / 256, 256>>>(W_in, pw1, nw1);
        int nw2 = (DINNER * DMODEL) / 4;
        round_tf32_kernel<<<(nw2 + 255) / 256, 256>>>(W_out, pw2, nw2);
    }

    // 1) xz = x @ W_in   (cvt-free 4-stage cp.async pipeline)
    dim3 g1(2 * DINNER / 128, M_ROWS / 128);
    gemm_tf32_pipe<<<g1, 256, PIPE_SMEM_BYTES>>>(pxr, pw1, pxz,
                                                 M_ROWS, 2 * DINNER, DMODEL);

    // 2) proj = silu(conv(xe)) @ W_xproj
    proj_conv_kernel<<<M_ROWS / 32, 256>>>(W_xproj, conv_w, conv_b);

    // 3) chunked scan
    scan_pass1<<<BATCH * NHEADS * NCHUNK, 128>>>(W_dt, b_dt, A_log, conv_w, conv_b);
    scan_pass2<<<(BATCH * NHEADS * HDIM * DSTATE) / 256, 256>>>();
    scan_pass3<<<BATCH * NHEADS * NCHUNK, 128>>>(W_dt, b_dt, A_log, D_skip, conv_w, conv_b);

    // 4) LN stats + apply + tf32 round -> g_yn
    ln_apply_kernel<<<M_ROWS, 256>>>(ln_g, ln_b);

    // 5) out = LN(y) @ W_out   (cvt-free pipeline)
    dim3 g2(DMODEL / 128, M_ROWS / 128);
    gemm_tf32_pipe<<<g2, 256, PIPE_SMEM_BYTES>>>(pyn, pw2, out,
                                                 M_ROWS, DMODEL, DINNER);
}